// round 9
// baseline (speedup 1.0000x reference)
#include <cuda_runtime.h>
#include <cuda_fp16.h>
#include <cstdint>
#include <math.h>

// Problem constants
#define BB 4
#define TT 2048
#define CC 1024
#define HH 16
#define DD 64
#define MM (BB*TT)          // 8192
#define NQKV (3*CC)         // 3072

// ---------------------------------------------------------------------------
// Scratch (__device__ globals; no allocation allowed)
// ---------------------------------------------------------------------------
__device__ __half g_Qh[BB*HH*TT*DD];                      // fp16, pre-scaled
__device__ __half g_Kh[BB*HH*TT*DD], g_Kl[BB*HH*TT*DD];   // fp16 hi/lo
__device__ __half g_Vh[BB*HH*TT*DD], g_Vl[BB*HH*TT*DD];
__device__ __half g_Xh[MM*CC];                            // x as fp16 (hi only)
__device__ __half g_Wqh[NQKV*CC], g_Wql[NQKV*CC];         // w_qkv hi/lo
__device__ __half g_Wph[CC*CC],  g_Wpl[CC*CC];            // w_proj hi/lo
__device__ __half g_Oh[MM*CC];                            // attn out (hi only)

// ---------------------------------------------------------------------------
// helpers
// ---------------------------------------------------------------------------
__device__ __forceinline__ uint32_t smem_u32(const void* p) {
    uint32_t a;
    asm("{ .reg .u64 t; cvta.to.shared.u64 t, %1; cvt.u32.u64 %0, t; }" : "=r"(a) : "l"(p));
    return a;
}
__device__ __forceinline__ void ldsm_x4(uint32_t& r0, uint32_t& r1, uint32_t& r2,
                                        uint32_t& r3, uint32_t addr) {
    asm volatile("ldmatrix.sync.aligned.m8n8.x4.shared.b16 {%0,%1,%2,%3}, [%4];"
                 : "=r"(r0), "=r"(r1), "=r"(r2), "=r"(r3) : "r"(addr));
}
__device__ __forceinline__ void ldsm_x4_t(uint32_t& r0, uint32_t& r1, uint32_t& r2,
                                          uint32_t& r3, uint32_t addr) {
    asm volatile("ldmatrix.sync.aligned.m8n8.x4.trans.shared.b16 {%0,%1,%2,%3}, [%4];"
                 : "=r"(r0), "=r"(r1), "=r"(r2), "=r"(r3) : "r"(addr));
}
// fp32-accumulator HMMA (hi pass)
__device__ __forceinline__ void mma_f16(float* c, const uint32_t* a, const uint32_t* b) {
    asm volatile("mma.sync.aligned.m16n8k16.row.col.f32.f16.f16.f32 "
                 "{%0,%1,%2,%3}, {%4,%5,%6,%7}, {%8,%9}, {%0,%1,%2,%3};"
                 : "+f"(c[0]), "+f"(c[1]), "+f"(c[2]), "+f"(c[3])
                 : "r"(a[0]), "r"(a[1]), "r"(a[2]), "r"(a[3]), "r"(b[0]), "r"(b[1]));
}
// fp16-accumulator HMMA (lo pass): D/C = 2 regs of packed half2
__device__ __forceinline__ void mma_f16acc(uint32_t* c, const uint32_t* a, const uint32_t* b) {
    asm volatile("mma.sync.aligned.m16n8k16.row.col.f16.f16.f16.f16 "
                 "{%0,%1}, {%2,%3,%4,%5}, {%6,%7}, {%0,%1};"
                 : "+r"(c[0]), "+r"(c[1])
                 : "r"(a[0]), "r"(a[1]), "r"(a[2]), "r"(a[3]), "r"(b[0]), "r"(b[1]));
}
// merge fp16 lo accumulator into fp32 accumulator (layout-identical pairs)
__device__ __forceinline__ void merge_lo(float* c, const uint32_t* cl) {
    const __half2 h0 = *reinterpret_cast<const __half2*>(&cl[0]);
    const __half2 h1 = *reinterpret_cast<const __half2*>(&cl[1]);
    c[0] += __low2float(h0); c[1] += __high2float(h0);
    c[2] += __low2float(h1); c[3] += __high2float(h1);
}
__device__ __forceinline__ void cp16(uint32_t dst, const void* src) {
    asm volatile("cp.async.cg.shared.global [%0], [%1], 16;" :: "r"(dst), "l"(src));
}
#define CP_COMMIT() asm volatile("cp.async.commit_group;" ::: "memory")
#define CP_WAIT(N)  asm volatile("cp.async.wait_group %0;" :: "n"(N) : "memory")

__device__ __forceinline__ void splith(float x, __half& h, __half& l) {
    h = __float2half_rn(x);
    l = __float2half_rn(x - __half2float(h));
}
__device__ __forceinline__ uint32_t packh(__half a, __half b) {
    __half2 t(a, b);
    return *reinterpret_cast<uint32_t*>(&t);
}
__device__ __forceinline__ uint32_t packf2(float x, float y) {
    __half2 t = __floats2half2_rn(x, y);
    return *reinterpret_cast<uint32_t*>(&t);
}

// ---------------------------------------------------------------------------
// conversion kernels
// ---------------------------------------------------------------------------
__global__ __launch_bounds__(256) void tohalf_kernel(const float* __restrict__ src,
                                                     __half* __restrict__ dst, int n4)
{
    int i = blockIdx.x * blockDim.x + threadIdx.x;
    if (i >= n4) return;
    float4 v = ((const float4*)src)[i];
    ((uint32_t*)dst)[i*2+0] = packf2(v.x, v.y);
    ((uint32_t*)dst)[i*2+1] = packf2(v.z, v.w);
}

__global__ __launch_bounds__(256) void splith_kernel(const float* __restrict__ src,
                                                     __half* __restrict__ hi,
                                                     __half* __restrict__ lo, int n4)
{
    int i = blockIdx.x * blockDim.x + threadIdx.x;
    if (i >= n4) return;
    float4 v = ((const float4*)src)[i];
    __half h[4], l[4];
    splith(v.x, h[0], l[0]); splith(v.y, h[1], l[1]);
    splith(v.z, h[2], l[2]); splith(v.w, h[3], l[3]);
    ((uint32_t*)hi)[i*2+0] = packh(h[0], h[1]);
    ((uint32_t*)hi)[i*2+1] = packh(h[2], h[3]);
    ((uint32_t*)lo)[i*2+0] = packh(l[0], l[1]);
    ((uint32_t*)lo)[i*2+1] = packh(l[2], l[3]);
}

// ---------------------------------------------------------------------------
// HMMA fp16 dual-acc GEMM: C = Ah*Bh (fp32 acc) + Ah*Bl (fp16 acc), merged.
// 512 threads / 16 warps, warp tile 32x32, CTA 128x128, BK=64, 3-stage cp.async.
// MODE 0: Q -> fp16 scaled, K/V -> fp16 hi/lo splits, [B,H,T,D]. MODE 1: fp32 out.
// ---------------------------------------------------------------------------
#define BKG 64
#define LDG_ 72
#define TILEG (128*LDG_)           // 9216 halves
#define STAGEG (3*TILEG)           // 27648 halves (Ah,Bh,Bl)
#define NSTG 3
#define GEMM_SMEM_BYTES (NSTG*STAGEG*2)   // 165888 B
#define GEMM_THREADS 512

template<int MODE>
__global__ __launch_bounds__(GEMM_THREADS, 1) void mma_gemm_kernel(
    const __half* __restrict__ Ah, const __half* __restrict__ Bh,
    const __half* __restrict__ Bl, float* __restrict__ out)
{
    extern __shared__ __half sm[];
    const uint32_t smb = smem_u32(sm);
    const int tid = threadIdx.x;
    const int lane = tid & 31, wid = tid >> 5;
    const int wm = (wid >> 2) * 32;
    const int wn = (wid & 3) * 32;
    const int n0 = blockIdx.x * 128;
    const int m0 = blockIdx.y * 128;

    const __half* srcs[3] = {
        Ah + (size_t)m0 * CC, Bh + (size_t)n0 * CC, Bl + (size_t)n0 * CC };

    const int NCH = CC / BKG;   // 16

    float acc[2][4][4];
    uint32_t accL[2][4][2];
    #pragma unroll
    for (int a = 0; a < 2; a++)
        #pragma unroll
        for (int b = 0; b < 4; b++) {
            #pragma unroll
            for (int c = 0; c < 4; c++) acc[a][b][c] = 0.0f;
            accL[a][b][0] = 0u; accL[a][b][1] = 0u;
        }

    const int a_m = ((lane >> 3) & 1) * 8 + (lane & 7);
    const int a_k = (lane >> 4) * 8;
    const int b_n = (lane >> 4) * 8 + (lane & 7);
    const int b_k = ((lane >> 3) & 1) * 8;

    auto issue_chunk = [&](int ch) {
        const uint32_t sbase = smb + (uint32_t)(ch % NSTG) * (STAGEG * 2);
        const int k0 = ch * BKG;
        #pragma unroll
        for (int l = 0; l < 6; l++) {
            const int o = l * GEMM_THREADS + tid;     // 0..3071
            const int tile = o >> 10;
            const int r = (o >> 3) & 127;
            const int c = (o & 7) * 8;
            cp16(sbase + (uint32_t)(tile * TILEG + r * LDG_ + c) * 2,
                 srcs[tile] + (size_t)r * CC + k0 + c);
        }
    };

    issue_chunk(0); CP_COMMIT();
    issue_chunk(1); CP_COMMIT();

    for (int ch = 0; ch < NCH; ch++) {
        CP_WAIT(1);
        __syncthreads();
        if (ch + 2 < NCH) issue_chunk(ch + 2);
        CP_COMMIT();

        const __half* buf = sm + (ch % NSTG) * STAGEG;

        #pragma unroll
        for (int kk = 0; kk < BKG; kk += 16) {
            uint32_t aH[2][4], bH[2][4], bL[2][4];
            #pragma unroll
            for (int mi = 0; mi < 2; mi++) {
                const int m = wm + mi * 16 + a_m;
                uint32_t ad = smem_u32(buf + m * LDG_ + kk + a_k);
                ldsm_x4(aH[mi][0], aH[mi][1], aH[mi][2], aH[mi][3], ad);
            }
            #pragma unroll
            for (int ni = 0; ni < 2; ni++) {
                const int n = wn + ni * 16 + b_n;
                uint32_t bd = smem_u32(buf + TILEG + n * LDG_ + kk + b_k);
                ldsm_x4(bH[ni][0], bH[ni][1], bH[ni][2], bH[ni][3], bd);
                ldsm_x4(bL[ni][0], bL[ni][1], bL[ni][2], bL[ni][3], bd + TILEG * 2);
            }
            // hi pass: fp32 acc
            #pragma unroll
            for (int mi = 0; mi < 2; mi++)
                #pragma unroll
                for (int nj = 0; nj < 4; nj++) {
                    uint32_t bh[2] = { bH[nj >> 1][(nj & 1) * 2], bH[nj >> 1][(nj & 1) * 2 + 1] };
                    mma_f16(acc[mi][nj], aH[mi], bh);
                }
            // lo pass: fp16 acc (predicted 2x rate)
            #pragma unroll
            for (int mi = 0; mi < 2; mi++)
                #pragma unroll
                for (int nj = 0; nj < 4; nj++) {
                    uint32_t bl[2] = { bL[nj >> 1][(nj & 1) * 2], bL[nj >> 1][(nj & 1) * 2 + 1] };
                    mma_f16acc(accL[mi][nj], aH[mi], bl);
                }
        }
    }

    // merge lo accumulators
    #pragma unroll
    for (int mi = 0; mi < 2; mi++)
        #pragma unroll
        for (int nj = 0; nj < 4; nj++)
            merge_lo(acc[mi][nj], accL[mi][nj]);

    // epilogue
    if (MODE == 0) {
        const int which = n0 >> 10;
        #pragma unroll
        for (int mi = 0; mi < 2; mi++)
            #pragma unroll
            for (int nj = 0; nj < 4; nj++) {
                const int row0 = m0 + wm + mi * 16 + (lane >> 2);
                const int col  = n0 + wn + nj * 8 + (lane & 3) * 2;
                const int o = col & 1023, hd = o >> 6, d = o & 63;
                #pragma unroll
                for (int h = 0; h < 2; h++) {
                    const int row = row0 + h * 8;
                    const int b = row >> 11, t = row & 2047;
                    const size_t off = ((size_t)(b * HH + hd) * TT + t) * DD + d;
                    const float x0 = acc[mi][nj][h*2], x1 = acc[mi][nj][h*2+1];
                    if (which == 0) {
                        *(uint32_t*)(g_Qh + off) = packf2(x0 * 0.125f, x1 * 0.125f);
                    } else {
                        __half* dh = (which == 1) ? g_Kh : g_Vh;
                        __half* dl = (which == 1) ? g_Kl : g_Vl;
                        __half h0, l0, h1, l1;
                        splith(x0, h0, l0); splith(x1, h1, l1);
                        *(uint32_t*)(dh + off) = packh(h0, h1);
                        *(uint32_t*)(dl + off) = packh(l0, l1);
                    }
                }
            }
    } else {
        #pragma unroll
        for (int mi = 0; mi < 2; mi++)
            #pragma unroll
            for (int nj = 0; nj < 4; nj++) {
                const int row0 = m0 + wm + mi * 16 + (lane >> 2);
                const int col  = n0 + wn + nj * 8 + (lane & 3) * 2;
                #pragma unroll
                for (int h = 0; h < 2; h++) {
                    const int row = row0 + h * 8;
                    float2 v = make_float2(acc[mi][nj][h*2], acc[mi][nj][h*2+1]);
                    *(float2*)(out + (size_t)row * CC + col) = v;
                }
            }
    }
}

// ---------------------------------------------------------------------------
// fp16 dual-acc tensor-core flash attention (causal).
// Q fp16 (pre-scaled); K,V fp16 hi/lo; hi pass fp32 acc, lo pass fp16 acc.
// 128 q/CTA, KTILE=64, 8 warps, cp.async 3-stage K/V pipeline.
// ---------------------------------------------------------------------------
#define AQT 128
#define AKT 64
#define ALD 72

struct AttnSmem {
    __half Q[AQT*ALD];
    __half KV[3][4][AKT*ALD];          // stage, {Kh,Kl,Vh,Vl}
};
#define ATTN_SMEM_BYTES ((int)sizeof(AttnSmem))   // 129024

__global__ __launch_bounds__(256, 1) void attn_mma_kernel()
{
    extern __shared__ char smraw[];
    AttnSmem& s = *(AttnSmem*)smraw;

    const int tid = threadIdx.x, lane = tid & 31, w = tid >> 5;
    const int bh = blockIdx.y;
    const int qi = gridDim.x - 1 - blockIdx.x;
    const int q0 = qi * AQT;
    const size_t base = (size_t)bh * TT * DD;
    const __half* kvsrc[4] = { g_Kh + base, g_Kl + base, g_Vh + base, g_Vl + base };
    const __half* Qsrc = g_Qh + base;

    const int nk = 2 * qi + 2;

    const int kr0 = tid >> 3, kr1 = 32 + (tid >> 3);
    const int kc = (tid & 7) * 8;

    auto issue_kv = [&](int kt) {
        const int st = kt % 3;
        const int k0 = kt * AKT;
        #pragma unroll
        for (int t = 0; t < 4; t++) {
            cp16(smem_u32(&s.KV[st][t][kr0 * ALD + kc]),
                 kvsrc[t] + (size_t)(k0 + kr0) * DD + kc);
            cp16(smem_u32(&s.KV[st][t][kr1 * ALD + kc]),
                 kvsrc[t] + (size_t)(k0 + kr1) * DD + kc);
        }
    };

    issue_kv(0); CP_COMMIT();
    issue_kv(1); CP_COMMIT();

    #pragma unroll
    for (int l = 0; l < 4; l++) {
        int idx = l * 256 + tid;
        int r = idx >> 3, d0 = (idx & 7) * 8;
        *(uint4*)&s.Q[r * ALD + d0] = *(const uint4*)(Qsrc + (size_t)(q0 + r) * DD + d0);
    }
    __syncthreads();

    const int a_m = ((lane >> 3) & 1) * 8 + (lane & 7);
    const int a_k = (lane >> 4) * 8;
    const int b_n = (lane >> 4) * 8 + (lane & 7);
    const int b_k = ((lane >> 3) & 1) * 8;
    const int t_r = ((lane >> 3) & 1) * 8 + (lane & 7);
    const int t_c = (lane >> 4) * 8;

    uint32_t qh[4][4];
    #pragma unroll
    for (int ks = 0; ks < 4; ks++) {
        uint32_t qa = smem_u32(&s.Q[(w * 16 + a_m) * ALD + ks * 16 + a_k]);
        ldsm_x4(qh[ks][0], qh[ks][1], qh[ks][2], qh[ks][3], qa);
    }

    float oacc[8][4];
    uint32_t oaccL[8][2];
    #pragma unroll
    for (int i = 0; i < 8; i++) {
        #pragma unroll
        for (int j = 0; j < 4; j++) oacc[i][j] = 0.0f;
        oaccL[i][0] = 0u; oaccL[i][1] = 0u;
    }
    float mrun[2] = { -1e30f, -1e30f }, lsum[2] = { 0.0f, 0.0f };

    const int qrow = q0 + w * 16 + (lane >> 2);

    for (int kt = 0; kt < nk; kt++) {
        const int k0 = kt * AKT;
        CP_WAIT(1);
        __syncthreads();
        if (kt + 2 < nk) issue_kv(kt + 2);
        CP_COMMIT();

        const int st = kt % 3;
        const __half* Khs = s.KV[st][0];
        const __half* Kls = s.KV[st][1];
        const __half* Vhs = s.KV[st][2];
        const __half* Vls = s.KV[st][3];

        // ---- S = Q*Kh (fp32 acc) + Q*Kl (fp16 acc) ----
        float sacc[8][4];
        uint32_t saccL[8][2];
        #pragma unroll
        for (int i = 0; i < 8; i++) {
            #pragma unroll
            for (int j = 0; j < 4; j++) sacc[i][j] = 0.0f;
            saccL[i][0] = 0u; saccL[i][1] = 0u;
        }

        #pragma unroll
        for (int nbp = 0; nbp < 4; nbp++) {
            #pragma unroll
            for (int ks = 0; ks < 4; ks++) {
                uint32_t kh4[4], kl4[4];
                uint32_t ka = smem_u32(Khs + (nbp * 16 + b_n) * ALD + ks * 16 + b_k);
                ldsm_x4(kh4[0], kh4[1], kh4[2], kh4[3], ka);
                uint32_t kb = smem_u32(Kls + (nbp * 16 + b_n) * ALD + ks * 16 + b_k);
                ldsm_x4(kl4[0], kl4[1], kl4[2], kl4[3], kb);
                #pragma unroll
                for (int hf = 0; hf < 2; hf++) {
                    const int nb = nbp * 2 + hf;
                    uint32_t bh2[2] = { kh4[hf*2], kh4[hf*2+1] };
                    uint32_t bl2[2] = { kl4[hf*2], kl4[hf*2+1] };
                    mma_f16(sacc[nb], qh[ks], bh2);
                    mma_f16acc(saccL[nb], qh[ks], bl2);
                }
            }
        }
        #pragma unroll
        for (int nb = 0; nb < 8; nb++) merge_lo(sacc[nb], saccL[nb]);

        // ---- causal mask ----
        if (k0 + 63 > qrow) {
            #pragma unroll
            for (int nb = 0; nb < 8; nb++)
                #pragma unroll
                for (int c = 0; c < 4; c++) {
                    const int kg = k0 + nb * 8 + (lane & 3) * 2 + (c & 1);
                    const int qg = qrow + ((c >= 2) ? 8 : 0);
                    if (kg > qg) sacc[nb][c] = -1e30f;
                }
        }

        // ---- online softmax ----
        float alf[2];
        #pragma unroll
        for (int r = 0; r < 2; r++) {
            float tm = -1e30f;
            #pragma unroll
            for (int nb = 0; nb < 8; nb++)
                tm = fmaxf(tm, fmaxf(sacc[nb][2*r], sacc[nb][2*r+1]));
            tm = fmaxf(tm, __shfl_xor_sync(0xffffffffu, tm, 1));
            tm = fmaxf(tm, __shfl_xor_sync(0xffffffffu, tm, 2));
            const float mn = fmaxf(mrun[r], tm);
            const float al = __expf(mrun[r] - mn);
            mrun[r] = mn; alf[r] = al;
            float rs = 0.0f;
            #pragma unroll
            for (int nb = 0; nb < 8; nb++) {
                float p0 = __expf(sacc[nb][2*r]   - mn);
                float p1 = __expf(sacc[nb][2*r+1] - mn);
                sacc[nb][2*r] = p0; sacc[nb][2*r+1] = p1;
                rs += p0 + p1;
            }
            rs += __shfl_xor_sync(0xffffffffu, rs, 1);
            rs += __shfl_xor_sync(0xffffffffu, rs, 2);
            lsum[r] = lsum[r] * al + rs;
            #pragma unroll
            for (int dn = 0; dn < 8; dn++) {
                oacc[dn][2*r] *= al; oacc[dn][2*r+1] *= al;
            }
        }
        // rescale fp16 lo accumulators by alpha (packed)
        {
            const __half2 a0 = __float2half2_rn(alf[0]);
            const __half2 a1 = __float2half2_rn(alf[1]);
            #pragma unroll
            for (int dn = 0; dn < 8; dn++) {
                __half2* p0 = reinterpret_cast<__half2*>(&oaccL[dn][0]);
                __half2* p1 = reinterpret_cast<__half2*>(&oaccL[dn][1]);
                *p0 = __hmul2(*p0, a0);
                *p1 = __hmul2(*p1, a1);
            }
        }

        // ---- O += P*Vh (fp32 acc) + P*Vl (fp16 acc) ----
        #pragma unroll
        for (int j = 0; j < 4; j++) {
            uint32_t ah[4];
            ah[0] = packf2(sacc[2*j][0],   sacc[2*j][1]);
            ah[1] = packf2(sacc[2*j][2],   sacc[2*j][3]);
            ah[2] = packf2(sacc[2*j+1][0], sacc[2*j+1][1]);
            ah[3] = packf2(sacc[2*j+1][2], sacc[2*j+1][3]);
            #pragma unroll
            for (int dnp = 0; dnp < 4; dnp++) {
                uint32_t vh4[4], vl4[4];
                uint32_t va = smem_u32(Vhs + (j * 16 + t_r) * ALD + dnp * 16 + t_c);
                ldsm_x4_t(vh4[0], vh4[1], vh4[2], vh4[3], va);
                uint32_t vb = smem_u32(Vls + (j * 16 + t_r) * ALD + dnp * 16 + t_c);
                ldsm_x4_t(vl4[0], vl4[1], vl4[2], vl4[3], vb);
                #pragma unroll
                for (int hf = 0; hf < 2; hf++) {
                    const int dn = dnp * 2 + hf;
                    uint32_t bh2[2] = { vh4[hf*2], vh4[hf*2+1] };
                    uint32_t bl2[2] = { vl4[hf*2], vl4[hf*2+1] };
                    mma_f16(oacc[dn], ah, bh2);
                    mma_f16acc(oaccL[dn], ah, bl2);
                }
            }
        }
    }

    // ---- epilogue: merge lo, normalize, write fp16 O in [B*T, C] ----
    const int b = bh >> 4, h = bh & 15;
    #pragma unroll
    for (int dn = 0; dn < 8; dn++) merge_lo(oacc[dn], oaccL[dn]);
    #pragma unroll
    for (int r = 0; r < 2; r++) {
        const float inv = 1.0f / lsum[r];
        const int row = q0 + w * 16 + (lane >> 2) + r * 8;
        const size_t off = (size_t)(b * TT + row) * CC + h * DD;
        #pragma unroll
        for (int dn = 0; dn < 8; dn++) {
            const int col = dn * 8 + (lane & 3) * 2;
            *(uint32_t*)(g_Oh + off + col) =
                packf2(oacc[dn][2*r] * inv, oacc[dn][2*r+1] * inv);
        }
    }
}

// ---------------------------------------------------------------------------
extern "C" void kernel_launch(void* const* d_in, const int* in_sizes, int n_in,
                              void* d_out, int out_size)
{
    const float* x     = (const float*)d_in[0];
    const float* wqkv  = (const float*)d_in[1];
    const float* wproj = (const float*)d_in[2];
    float* out = (float*)d_out;

    cudaFuncSetAttribute((const void*)attn_mma_kernel,
                         cudaFuncAttributeMaxDynamicSharedMemorySize, ATTN_SMEM_BYTES);
    cudaFuncSetAttribute((const void*)mma_gemm_kernel<0>,
                         cudaFuncAttributeMaxDynamicSharedMemorySize, GEMM_SMEM_BYTES);
    cudaFuncSetAttribute((const void*)mma_gemm_kernel<1>,
                         cudaFuncAttributeMaxDynamicSharedMemorySize, GEMM_SMEM_BYTES);

    __half *xh, *wqh, *wql, *wph, *wpl, *oh;
    cudaGetSymbolAddress((void**)&xh,  g_Xh);
    cudaGetSymbolAddress((void**)&wqh, g_Wqh); cudaGetSymbolAddress((void**)&wql, g_Wql);
    cudaGetSymbolAddress((void**)&wph, g_Wph); cudaGetSymbolAddress((void**)&wpl, g_Wpl);
    cudaGetSymbolAddress((void**)&oh,  g_Oh);

    tohalf_kernel<<<(MM*CC/4 + 255)/256, 256>>>(x, xh, MM*CC/4);
    splith_kernel<<<(NQKV*CC/4 + 255)/256, 256>>>(wqkv, wqh, wql, NQKV*CC/4);
    splith_kernel<<<(CC*CC/4 + 255)/256, 256>>>(wproj, wph, wpl, CC*CC/4);

    mma_gemm_kernel<0><<<dim3(NQKV/128, MM/128), GEMM_THREADS, GEMM_SMEM_BYTES>>>(
        xh, wqh, wql, nullptr);

    attn_mma_kernel<<<dim3(TT/AQT, BB*HH), 256, ATTN_SMEM_BYTES>>>();

    mma_gemm_kernel<1><<<dim3(CC/128, MM/128), GEMM_THREADS, GEMM_SMEM_BYTES>>>(
        oh, wph, wpl, out);
}

// round 10
// speedup vs baseline: 1.7003x; 1.7003x over previous
#include <cuda_runtime.h>
#include <cuda_fp16.h>
#include <cstdint>
#include <math.h>

// Problem constants
#define BB 4
#define TT 2048
#define CC 1024
#define HH 16
#define DD 64
#define MM (BB*TT)          // 8192
#define NQKV (3*CC)         // 3072

// ---------------------------------------------------------------------------
// Scratch (__device__ globals; no allocation allowed)
// ---------------------------------------------------------------------------
__device__ __half g_Qh[BB*HH*TT*DD];          // fp16, pre-scaled by 0.125
__device__ __half g_Kh[BB*HH*TT*DD];
__device__ __half g_Vh[BB*HH*TT*DD];
__device__ __half g_Xh[MM*CC];                // x as fp16
__device__ __half g_Wqh[NQKV*CC];             // w_qkv fp16
__device__ __half g_Wph[CC*CC];               // w_proj fp16
__device__ __half g_Oh[MM*CC];                // attn out fp16, [B*T, C]

// ---------------------------------------------------------------------------
// helpers
// ---------------------------------------------------------------------------
__device__ __forceinline__ uint32_t smem_u32(const void* p) {
    uint32_t a;
    asm("{ .reg .u64 t; cvta.to.shared.u64 t, %1; cvt.u32.u64 %0, t; }" : "=r"(a) : "l"(p));
    return a;
}
__device__ __forceinline__ void ldsm_x4(uint32_t& r0, uint32_t& r1, uint32_t& r2,
                                        uint32_t& r3, uint32_t addr) {
    asm volatile("ldmatrix.sync.aligned.m8n8.x4.shared.b16 {%0,%1,%2,%3}, [%4];"
                 : "=r"(r0), "=r"(r1), "=r"(r2), "=r"(r3) : "r"(addr));
}
__device__ __forceinline__ void ldsm_x4_t(uint32_t& r0, uint32_t& r1, uint32_t& r2,
                                          uint32_t& r3, uint32_t addr) {
    asm volatile("ldmatrix.sync.aligned.m8n8.x4.trans.shared.b16 {%0,%1,%2,%3}, [%4];"
                 : "=r"(r0), "=r"(r1), "=r"(r2), "=r"(r3) : "r"(addr));
}
__device__ __forceinline__ void mma_f16(float* c, const uint32_t* a, const uint32_t* b) {
    asm volatile("mma.sync.aligned.m16n8k16.row.col.f32.f16.f16.f32 "
                 "{%0,%1,%2,%3}, {%4,%5,%6,%7}, {%8,%9}, {%0,%1,%2,%3};"
                 : "+f"(c[0]), "+f"(c[1]), "+f"(c[2]), "+f"(c[3])
                 : "r"(a[0]), "r"(a[1]), "r"(a[2]), "r"(a[3]), "r"(b[0]), "r"(b[1]));
}
__device__ __forceinline__ void cp16(uint32_t dst, const void* src) {
    asm volatile("cp.async.cg.shared.global [%0], [%1], 16;" :: "r"(dst), "l"(src));
}
#define CP_COMMIT() asm volatile("cp.async.commit_group;" ::: "memory")
#define CP_WAIT(N)  asm volatile("cp.async.wait_group %0;" :: "n"(N) : "memory")

__device__ __forceinline__ uint32_t packf2(float x, float y) {
    __half2 t = __floats2half2_rn(x, y);   // x -> low half
    return *reinterpret_cast<uint32_t*>(&t);
}

// ---------------------------------------------------------------------------
// fp32 -> fp16 conversion
// ---------------------------------------------------------------------------
__global__ __launch_bounds__(256) void tohalf_kernel(const float* __restrict__ src,
                                                     __half* __restrict__ dst, int n4)
{
    int i = blockIdx.x * blockDim.x + threadIdx.x;
    if (i >= n4) return;
    float4 v = ((const float4*)src)[i];
    ((uint32_t*)dst)[i*2+0] = packf2(v.x, v.y);
    ((uint32_t*)dst)[i*2+1] = packf2(v.z, v.w);
}

// ---------------------------------------------------------------------------
// HMMA fp16 single-pass GEMM: C[m,n] = sum_k Ah[m,k]*Bh[n,k]
// 512 threads / 16 warps, warp tile 32x32, CTA 128x128, BK=64, 3-stage cp.async.
// MODE 0: Q -> fp16 scaled 0.125, K/V fp16, [B,H,T,D]. MODE 1: fp32 out [M,1024].
// ---------------------------------------------------------------------------
#define BKG 64
#define LDG_ 72
#define TILEG (128*LDG_)           // 9216 halves
#define STAGEG (2*TILEG)           // 18432 halves (Ah,Bh)
#define NSTG 3
#define GEMM_SMEM_BYTES (NSTG*STAGEG*2)   // 110592 B
#define GEMM_THREADS 512

template<int MODE>
__global__ __launch_bounds__(GEMM_THREADS, 1) void mma_gemm_kernel(
    const __half* __restrict__ Ah, const __half* __restrict__ Bh,
    float* __restrict__ out)
{
    extern __shared__ __half sm[];
    const uint32_t smb = smem_u32(sm);
    const int tid = threadIdx.x;
    const int lane = tid & 31, wid = tid >> 5;
    const int wm = (wid >> 2) * 32;
    const int wn = (wid & 3) * 32;
    const int n0 = blockIdx.x * 128;
    const int m0 = blockIdx.y * 128;

    const __half* srcs[2] = { Ah + (size_t)m0 * CC, Bh + (size_t)n0 * CC };

    const int NCH = CC / BKG;   // 16

    float acc[2][4][4];
    #pragma unroll
    for (int a = 0; a < 2; a++)
        #pragma unroll
        for (int b = 0; b < 4; b++)
            #pragma unroll
            for (int c = 0; c < 4; c++) acc[a][b][c] = 0.0f;

    const int a_m = ((lane >> 3) & 1) * 8 + (lane & 7);
    const int a_k = (lane >> 4) * 8;
    const int b_n = (lane >> 4) * 8 + (lane & 7);
    const int b_k = ((lane >> 3) & 1) * 8;

    // one 64-K chunk = 2 tiles of 128x64 fp16; 4 cp16/thread
    auto issue_chunk = [&](int ch) {
        const uint32_t sbase = smb + (uint32_t)(ch % NSTG) * (STAGEG * 2);
        const int k0 = ch * BKG;
        #pragma unroll
        for (int l = 0; l < 4; l++) {
            const int o = l * GEMM_THREADS + tid;     // 0..2047
            const int tile = o >> 10;
            const int r = (o >> 3) & 127;
            const int c = (o & 7) * 8;
            cp16(sbase + (uint32_t)(tile * TILEG + r * LDG_ + c) * 2,
                 srcs[tile] + (size_t)r * CC + k0 + c);
        }
    };

    issue_chunk(0); CP_COMMIT();
    issue_chunk(1); CP_COMMIT();

    for (int ch = 0; ch < NCH; ch++) {
        CP_WAIT(1);
        __syncthreads();
        if (ch + 2 < NCH) issue_chunk(ch + 2);
        CP_COMMIT();

        const __half* buf = sm + (ch % NSTG) * STAGEG;

        #pragma unroll
        for (int kk = 0; kk < BKG; kk += 16) {
            uint32_t aH[2][4], bH[2][4];
            #pragma unroll
            for (int mi = 0; mi < 2; mi++) {
                const int m = wm + mi * 16 + a_m;
                uint32_t ad = smem_u32(buf + m * LDG_ + kk + a_k);
                ldsm_x4(aH[mi][0], aH[mi][1], aH[mi][2], aH[mi][3], ad);
            }
            #pragma unroll
            for (int ni = 0; ni < 2; ni++) {
                const int n = wn + ni * 16 + b_n;
                uint32_t bd = smem_u32(buf + TILEG + n * LDG_ + kk + b_k);
                ldsm_x4(bH[ni][0], bH[ni][1], bH[ni][2], bH[ni][3], bd);
            }
            #pragma unroll
            for (int mi = 0; mi < 2; mi++)
                #pragma unroll
                for (int nj = 0; nj < 4; nj++) {
                    uint32_t bh[2] = { bH[nj >> 1][(nj & 1) * 2], bH[nj >> 1][(nj & 1) * 2 + 1] };
                    mma_f16(acc[mi][nj], aH[mi], bh);
                }
        }
    }

    // epilogue
    if (MODE == 0) {
        const int which = n0 >> 10;
        __half* dst = (which == 0) ? g_Qh : ((which == 1) ? g_Kh : g_Vh);
        const float scl = (which == 0) ? 0.125f : 1.0f;
        #pragma unroll
        for (int mi = 0; mi < 2; mi++)
            #pragma unroll
            for (int nj = 0; nj < 4; nj++) {
                const int row0 = m0 + wm + mi * 16 + (lane >> 2);
                const int col  = n0 + wn + nj * 8 + (lane & 3) * 2;
                const int o = col & 1023, hd = o >> 6, d = o & 63;
                #pragma unroll
                for (int h = 0; h < 2; h++) {
                    const int row = row0 + h * 8;
                    const int b = row >> 11, t = row & 2047;
                    const size_t off = ((size_t)(b * HH + hd) * TT + t) * DD + d;
                    *(uint32_t*)(dst + off) =
                        packf2(acc[mi][nj][h*2] * scl, acc[mi][nj][h*2+1] * scl);
                }
            }
    } else {
        #pragma unroll
        for (int mi = 0; mi < 2; mi++)
            #pragma unroll
            for (int nj = 0; nj < 4; nj++) {
                const int row0 = m0 + wm + mi * 16 + (lane >> 2);
                const int col  = n0 + wn + nj * 8 + (lane & 3) * 2;
                #pragma unroll
                for (int h = 0; h < 2; h++) {
                    const int row = row0 + h * 8;
                    float2 v = make_float2(acc[mi][nj][h*2], acc[mi][nj][h*2+1]);
                    *(float2*)(out + (size_t)row * CC + col) = v;
                }
            }
    }
}

// ---------------------------------------------------------------------------
// fp16 single-pass tensor-core flash attention (causal).
// Q fp16 (pre-scaled); K,V fp16. 128 q/CTA, KTILE=64, 8 warps,
// cp.async 3-stage K/V pipeline. smem 73.7 KB -> 2 CTAs/SM.
// ---------------------------------------------------------------------------
#define AQT 128
#define AKT 64
#define ALD 72

struct AttnSmem {
    __half Q[AQT*ALD];
    __half KV[3][2][AKT*ALD];          // stage, {Kh,Vh}
};
#define ATTN_SMEM_BYTES ((int)sizeof(AttnSmem))   // 73728

__global__ __launch_bounds__(256, 2) void attn_mma_kernel()
{
    extern __shared__ char smraw[];
    AttnSmem& s = *(AttnSmem*)smraw;

    const int tid = threadIdx.x, lane = tid & 31, w = tid >> 5;
    const int bh = blockIdx.y;
    const int qi = gridDim.x - 1 - blockIdx.x;
    const int q0 = qi * AQT;
    const size_t base = (size_t)bh * TT * DD;
    const __half* kvsrc[2] = { g_Kh + base, g_Vh + base };
    const __half* Qsrc = g_Qh + base;

    const int nk = 2 * qi + 2;

    const int kr0 = tid >> 3, kr1 = 32 + (tid >> 3);
    const int kc = (tid & 7) * 8;

    auto issue_kv = [&](int kt) {
        const int st = kt % 3;
        const int k0 = kt * AKT;
        #pragma unroll
        for (int t = 0; t < 2; t++) {
            cp16(smem_u32(&s.KV[st][t][kr0 * ALD + kc]),
                 kvsrc[t] + (size_t)(k0 + kr0) * DD + kc);
            cp16(smem_u32(&s.KV[st][t][kr1 * ALD + kc]),
                 kvsrc[t] + (size_t)(k0 + kr1) * DD + kc);
        }
    };

    issue_kv(0); CP_COMMIT();
    issue_kv(1); CP_COMMIT();

    // Q tile -> smem
    #pragma unroll
    for (int l = 0; l < 4; l++) {
        int idx = l * 256 + tid;
        int r = idx >> 3, d0 = (idx & 7) * 8;
        *(uint4*)&s.Q[r * ALD + d0] = *(const uint4*)(Qsrc + (size_t)(q0 + r) * DD + d0);
    }
    __syncthreads();

    const int a_m = ((lane >> 3) & 1) * 8 + (lane & 7);
    const int a_k = (lane >> 4) * 8;
    const int b_n = (lane >> 4) * 8 + (lane & 7);
    const int b_k = ((lane >> 3) & 1) * 8;
    const int t_r = ((lane >> 3) & 1) * 8 + (lane & 7);
    const int t_c = (lane >> 4) * 8;

    uint32_t qh[4][4];
    #pragma unroll
    for (int ks = 0; ks < 4; ks++) {
        uint32_t qa = smem_u32(&s.Q[(w * 16 + a_m) * ALD + ks * 16 + a_k]);
        ldsm_x4(qh[ks][0], qh[ks][1], qh[ks][2], qh[ks][3], qa);
    }

    float oacc[8][4];
    #pragma unroll
    for (int i = 0; i < 8; i++)
        #pragma unroll
        for (int j = 0; j < 4; j++) oacc[i][j] = 0.0f;
    float mrun[2] = { -1e30f, -1e30f }, lsum[2] = { 0.0f, 0.0f };

    const int qrow = q0 + w * 16 + (lane >> 2);

    for (int kt = 0; kt < nk; kt++) {
        const int k0 = kt * AKT;
        CP_WAIT(1);
        __syncthreads();
        if (kt + 2 < nk) issue_kv(kt + 2);
        CP_COMMIT();

        const int st = kt % 3;
        const __half* Khs = s.KV[st][0];
        const __half* Vhs = s.KV[st][1];

        // ---- S = Q K^T ----
        float sacc[8][4];
        #pragma unroll
        for (int i = 0; i < 8; i++)
            #pragma unroll
            for (int j = 0; j < 4; j++) sacc[i][j] = 0.0f;

        #pragma unroll
        for (int nbp = 0; nbp < 4; nbp++) {
            #pragma unroll
            for (int ks = 0; ks < 4; ks++) {
                uint32_t kh4[4];
                uint32_t ka = smem_u32(Khs + (nbp * 16 + b_n) * ALD + ks * 16 + b_k);
                ldsm_x4(kh4[0], kh4[1], kh4[2], kh4[3], ka);
                #pragma unroll
                for (int hf = 0; hf < 2; hf++) {
                    const int nb = nbp * 2 + hf;
                    uint32_t bh2[2] = { kh4[hf*2], kh4[hf*2+1] };
                    mma_f16(sacc[nb], qh[ks], bh2);
                }
            }
        }

        // ---- causal mask ----
        if (k0 + 63 > qrow) {
            #pragma unroll
            for (int nb = 0; nb < 8; nb++)
                #pragma unroll
                for (int c = 0; c < 4; c++) {
                    const int kg = k0 + nb * 8 + (lane & 3) * 2 + (c & 1);
                    const int qg = qrow + ((c >= 2) ? 8 : 0);
                    if (kg > qg) sacc[nb][c] = -1e30f;
                }
        }

        // ---- online softmax ----
        #pragma unroll
        for (int r = 0; r < 2; r++) {
            float tm = -1e30f;
            #pragma unroll
            for (int nb = 0; nb < 8; nb++)
                tm = fmaxf(tm, fmaxf(sacc[nb][2*r], sacc[nb][2*r+1]));
            tm = fmaxf(tm, __shfl_xor_sync(0xffffffffu, tm, 1));
            tm = fmaxf(tm, __shfl_xor_sync(0xffffffffu, tm, 2));
            const float mn = fmaxf(mrun[r], tm);
            const float al = __expf(mrun[r] - mn);
            mrun[r] = mn;
            float rs = 0.0f;
            #pragma unroll
            for (int nb = 0; nb < 8; nb++) {
                float p0 = __expf(sacc[nb][2*r]   - mn);
                float p1 = __expf(sacc[nb][2*r+1] - mn);
                sacc[nb][2*r] = p0; sacc[nb][2*r+1] = p1;
                rs += p0 + p1;
            }
            rs += __shfl_xor_sync(0xffffffffu, rs, 1);
            rs += __shfl_xor_sync(0xffffffffu, rs, 2);
            lsum[r] = lsum[r] * al + rs;
            #pragma unroll
            for (int dn = 0; dn < 8; dn++) {
                oacc[dn][2*r] *= al; oacc[dn][2*r+1] *= al;
            }
        }

        // ---- O += P V (trans-ldmatrix V) ----
        #pragma unroll
        for (int j = 0; j < 4; j++) {
            uint32_t ah[4];
            ah[0] = packf2(sacc[2*j][0],   sacc[2*j][1]);
            ah[1] = packf2(sacc[2*j][2],   sacc[2*j][3]);
            ah[2] = packf2(sacc[2*j+1][0], sacc[2*j+1][1]);
            ah[3] = packf2(sacc[2*j+1][2], sacc[2*j+1][3]);
            #pragma unroll
            for (int dnp = 0; dnp < 4; dnp++) {
                uint32_t vh4[4];
                uint32_t va = smem_u32(Vhs + (j * 16 + t_r) * ALD + dnp * 16 + t_c);
                ldsm_x4_t(vh4[0], vh4[1], vh4[2], vh4[3], va);
                #pragma unroll
                for (int hf = 0; hf < 2; hf++) {
                    const int dn = dnp * 2 + hf;
                    uint32_t bh2[2] = { vh4[hf*2], vh4[hf*2+1] };
                    mma_f16(oacc[dn], ah, bh2);
                }
            }
        }
    }

    // ---- epilogue: normalize, write fp16 O in [B*T, C] ----
    const int b = bh >> 4, h = bh & 15;
    #pragma unroll
    for (int r = 0; r < 2; r++) {
        const float inv = 1.0f / lsum[r];
        const int row = q0 + w * 16 + (lane >> 2) + r * 8;
        const size_t off = (size_t)(b * TT + row) * CC + h * DD;
        #pragma unroll
        for (int dn = 0; dn < 8; dn++) {
            const int col = dn * 8 + (lane & 3) * 2;
            *(uint32_t*)(g_Oh + off + col) =
                packf2(oacc[dn][2*r] * inv, oacc[dn][2*r+1] * inv);
        }
    }
}

// ---------------------------------------------------------------------------
extern "C" void kernel_launch(void* const* d_in, const int* in_sizes, int n_in,
                              void* d_out, int out_size)
{
    const float* x     = (const float*)d_in[0];
    const float* wqkv  = (const float*)d_in[1];
    const float* wproj = (const float*)d_in[2];
    float* out = (float*)d_out;

    cudaFuncSetAttribute((const void*)attn_mma_kernel,
                         cudaFuncAttributeMaxDynamicSharedMemorySize, ATTN_SMEM_BYTES);
    cudaFuncSetAttribute((const void*)mma_gemm_kernel<0>,
                         cudaFuncAttributeMaxDynamicSharedMemorySize, GEMM_SMEM_BYTES);
    cudaFuncSetAttribute((const void*)mma_gemm_kernel<1>,
                         cudaFuncAttributeMaxDynamicSharedMemorySize, GEMM_SMEM_BYTES);

    __half *xh, *wqh, *wph, *oh;
    cudaGetSymbolAddress((void**)&xh,  g_Xh);
    cudaGetSymbolAddress((void**)&wqh, g_Wqh);
    cudaGetSymbolAddress((void**)&wph, g_Wph);
    cudaGetSymbolAddress((void**)&oh,  g_Oh);

    tohalf_kernel<<<(MM*CC/4 + 255)/256, 256>>>(x, xh, MM*CC/4);
    tohalf_kernel<<<(NQKV*CC/4 + 255)/256, 256>>>(wqkv, wqh, NQKV*CC/4);
    tohalf_kernel<<<(CC*CC/4 + 255)/256, 256>>>(wproj, wph, CC*CC/4);

    mma_gemm_kernel<0><<<dim3(NQKV/128, MM/128), GEMM_THREADS, GEMM_SMEM_BYTES>>>(
        xh, wqh, nullptr);

    attn_mma_kernel<<<dim3(TT/AQT, BB*HH), 256, ATTN_SMEM_BYTES>>>();

    mma_gemm_kernel<1><<<dim3(CC/128, MM/128), GEMM_THREADS, GEMM_SMEM_BYTES>>>(
        oh, wph, out);
}

// round 11
// speedup vs baseline: 1.8996x; 1.1172x over previous
#include <cuda_runtime.h>
#include <cuda_fp16.h>
#include <cstdint>
#include <math.h>

// Problem constants
#define BB 4
#define TT 2048
#define CC 1024
#define HH 16
#define DD 64
#define MM (BB*TT)          // 8192
#define NQKV (3*CC)         // 3072

// ---------------------------------------------------------------------------
// Scratch (__device__ globals; no allocation allowed)
// ---------------------------------------------------------------------------
__device__ __half g_Qh[BB*HH*TT*DD];          // fp16, pre-scaled by 0.125
__device__ __half g_Kh[BB*HH*TT*DD];
__device__ __half g_Vh[BB*HH*TT*DD];
__device__ __half g_Xh[MM*CC];                // x as fp16
__device__ __half g_Wqh[NQKV*CC];             // w_qkv fp16
__device__ __half g_Wph[CC*CC];               // w_proj fp16
__device__ __half g_Oh[MM*CC];                // attn out fp16, [B*T, C]

// ---------------------------------------------------------------------------
// helpers
// ---------------------------------------------------------------------------
__device__ __forceinline__ uint32_t smem_u32(const void* p) {
    uint32_t a;
    asm("{ .reg .u64 t; cvta.to.shared.u64 t, %1; cvt.u32.u64 %0, t; }" : "=r"(a) : "l"(p));
    return a;
}
__device__ __forceinline__ void ldsm_x4(uint32_t& r0, uint32_t& r1, uint32_t& r2,
                                        uint32_t& r3, uint32_t addr) {
    asm volatile("ldmatrix.sync.aligned.m8n8.x4.shared.b16 {%0,%1,%2,%3}, [%4];"
                 : "=r"(r0), "=r"(r1), "=r"(r2), "=r"(r3) : "r"(addr));
}
__device__ __forceinline__ void ldsm_x4_t(uint32_t& r0, uint32_t& r1, uint32_t& r2,
                                          uint32_t& r3, uint32_t addr) {
    asm volatile("ldmatrix.sync.aligned.m8n8.x4.trans.shared.b16 {%0,%1,%2,%3}, [%4];"
                 : "=r"(r0), "=r"(r1), "=r"(r2), "=r"(r3) : "r"(addr));
}
__device__ __forceinline__ void mma_f16(float* c, const uint32_t* a, const uint32_t* b) {
    asm volatile("mma.sync.aligned.m16n8k16.row.col.f32.f16.f16.f32 "
                 "{%0,%1,%2,%3}, {%4,%5,%6,%7}, {%8,%9}, {%0,%1,%2,%3};"
                 : "+f"(c[0]), "+f"(c[1]), "+f"(c[2]), "+f"(c[3])
                 : "r"(a[0]), "r"(a[1]), "r"(a[2]), "r"(a[3]), "r"(b[0]), "r"(b[1]));
}
__device__ __forceinline__ void cp16(uint32_t dst, const void* src) {
    asm volatile("cp.async.cg.shared.global [%0], [%1], 16;" :: "r"(dst), "l"(src));
}
#define CP_COMMIT() asm volatile("cp.async.commit_group;" ::: "memory")
#define CP_WAIT(N)  asm volatile("cp.async.wait_group %0;" :: "n"(N) : "memory")

__device__ __forceinline__ uint32_t packf2(float x, float y) {
    __half2 t = __floats2half2_rn(x, y);   // x -> low half
    return *reinterpret_cast<uint32_t*>(&t);
}

// ---------------------------------------------------------------------------
// fused fp32 -> fp16 conversion (x, w_qkv, w_proj in one launch)
// ---------------------------------------------------------------------------
#define N4_X    (MM*CC/4)      // 2097152
#define N4_WQ   (NQKV*CC/4)    //  786432
#define N4_WP   (CC*CC/4)      //  262144
#define N4_ALL  (N4_X + N4_WQ + N4_WP)

__global__ __launch_bounds__(256) void convert_all_kernel(
    const float* __restrict__ x, const float* __restrict__ wq,
    const float* __restrict__ wp)
{
    int i = blockIdx.x * blockDim.x + threadIdx.x;
    if (i >= N4_ALL) return;
    const float* src; __half* dst; int j;
    if (i < N4_X)               { src = x;  dst = g_Xh;  j = i; }
    else if (i < N4_X + N4_WQ)  { src = wq; dst = g_Wqh; j = i - N4_X; }
    else                        { src = wp; dst = g_Wph; j = i - N4_X - N4_WQ; }
    float4 v = ((const float4*)src)[j];
    ((uint32_t*)dst)[j*2+0] = packf2(v.x, v.y);
    ((uint32_t*)dst)[j*2+1] = packf2(v.z, v.w);
}

// ---------------------------------------------------------------------------
// HMMA fp16 single-pass GEMM: C[m,n] = sum_k Ah[m,k]*Bh[n,k]
// 512 threads / 16 warps, warp tile 32x64, CTA 128x256, BK=64, 3-stage cp.async.
// Per k16 per warp: 2 A-ldsm + 4 B-ldsm : 16 MMA.
// MODE 0: Q -> fp16 scaled 0.125, K/V fp16, [B,H,T,D]. MODE 1: fp32 out [M,1024].
// ---------------------------------------------------------------------------
#define BKG 64
#define LDG_ 72
#define TILEA (128*LDG_)                  // 9216 halves
#define TILEB (256*LDG_)                  // 18432 halves
#define STAGEG (TILEA + TILEB)            // 27648 halves
#define NSTG 3
#define GEMM_SMEM_BYTES (NSTG*STAGEG*2)   // 165888 B
#define GEMM_THREADS 512

template<int MODE>
__global__ __launch_bounds__(GEMM_THREADS, 1) void mma_gemm_kernel(
    const __half* __restrict__ Ah, const __half* __restrict__ Bh,
    float* __restrict__ out)
{
    extern __shared__ __half sm[];
    const uint32_t smb = smem_u32(sm);
    const int tid = threadIdx.x;
    const int lane = tid & 31, wid = tid >> 5;
    const int wm = (wid >> 2) * 32;                // 0,32,64,96
    const int wn = (wid & 3) * 64;                 // 0,64,128,192
    const int n0 = blockIdx.x * 256;
    const int m0 = blockIdx.y * 128;

    const __half* Asrc = Ah + (size_t)m0 * CC;
    const __half* Bsrc = Bh + (size_t)n0 * CC;

    const int NCH = CC / BKG;   // 16

    float acc[2][8][4];
    #pragma unroll
    for (int a = 0; a < 2; a++)
        #pragma unroll
        for (int b = 0; b < 8; b++)
            #pragma unroll
            for (int c = 0; c < 4; c++) acc[a][b][c] = 0.0f;

    const int a_m = ((lane >> 3) & 1) * 8 + (lane & 7);
    const int a_k = (lane >> 4) * 8;
    const int b_n = (lane >> 4) * 8 + (lane & 7);
    const int b_k = ((lane >> 3) & 1) * 8;

    // one 64-K chunk: A 128x64 (1024 cp16) + B 256x64 (2048 cp16); 6 cp16/thread
    auto issue_chunk = [&](int ch) {
        const uint32_t sbase = smb + (uint32_t)(ch % NSTG) * (STAGEG * 2);
        const int k0 = ch * BKG;
        #pragma unroll
        for (int l = 0; l < 6; l++) {
            const int o = l * GEMM_THREADS + tid;     // 0..3071
            if (o < 1024) {
                const int r = o >> 3, c = (o & 7) * 8;
                cp16(sbase + (uint32_t)(r * LDG_ + c) * 2,
                     Asrc + (size_t)r * CC + k0 + c);
            } else {
                const int p = o - 1024;
                const int r = p >> 3, c = (p & 7) * 8;
                cp16(sbase + (uint32_t)(TILEA + r * LDG_ + c) * 2,
                     Bsrc + (size_t)r * CC + k0 + c);
            }
        }
    };

    issue_chunk(0); CP_COMMIT();
    issue_chunk(1); CP_COMMIT();

    for (int ch = 0; ch < NCH; ch++) {
        CP_WAIT(1);
        __syncthreads();
        if (ch + 2 < NCH) issue_chunk(ch + 2);
        CP_COMMIT();

        const uint32_t buf = smb + (uint32_t)(ch % NSTG) * (STAGEG * 2);

        #pragma unroll
        for (int kk = 0; kk < BKG; kk += 16) {
            uint32_t aH[2][4], bH[4][4];
            #pragma unroll
            for (int mi = 0; mi < 2; mi++) {
                const int m = wm + mi * 16 + a_m;
                ldsm_x4(aH[mi][0], aH[mi][1], aH[mi][2], aH[mi][3],
                        buf + (uint32_t)(m * LDG_ + kk + a_k) * 2);
            }
            #pragma unroll
            for (int ni = 0; ni < 4; ni++) {
                const int n = wn + ni * 16 + b_n;
                ldsm_x4(bH[ni][0], bH[ni][1], bH[ni][2], bH[ni][3],
                        buf + (uint32_t)(TILEA + n * LDG_ + kk + b_k) * 2);
            }
            #pragma unroll
            for (int mi = 0; mi < 2; mi++)
                #pragma unroll
                for (int nj = 0; nj < 8; nj++) {
                    uint32_t bh[2] = { bH[nj >> 1][(nj & 1) * 2], bH[nj >> 1][(nj & 1) * 2 + 1] };
                    mma_f16(acc[mi][nj], aH[mi], bh);
                }
        }
    }

    // epilogue
    if (MODE == 0) {
        const int which = n0 >> 10;    // 256-col range never straddles a boundary
        __half* dst = (which == 0) ? g_Qh : ((which == 1) ? g_Kh : g_Vh);
        const float scl = (which == 0) ? 0.125f : 1.0f;
        #pragma unroll
        for (int mi = 0; mi < 2; mi++)
            #pragma unroll
            for (int nj = 0; nj < 8; nj++) {
                const int row0 = m0 + wm + mi * 16 + (lane >> 2);
                const int col  = n0 + wn + nj * 8 + (lane & 3) * 2;
                const int o = col & 1023, hd = o >> 6, d = o & 63;
                #pragma unroll
                for (int h = 0; h < 2; h++) {
                    const int row = row0 + h * 8;
                    const int b = row >> 11, t = row & 2047;
                    const size_t off = ((size_t)(b * HH + hd) * TT + t) * DD + d;
                    *(uint32_t*)(dst + off) =
                        packf2(acc[mi][nj][h*2] * scl, acc[mi][nj][h*2+1] * scl);
                }
            }
    } else {
        #pragma unroll
        for (int mi = 0; mi < 2; mi++)
            #pragma unroll
            for (int nj = 0; nj < 8; nj++) {
                const int row0 = m0 + wm + mi * 16 + (lane >> 2);
                const int col  = n0 + wn + nj * 8 + (lane & 3) * 2;
                #pragma unroll
                for (int h = 0; h < 2; h++) {
                    const int row = row0 + h * 8;
                    float2 v = make_float2(acc[mi][nj][h*2], acc[mi][nj][h*2+1]);
                    *(float2*)(out + (size_t)row * CC + col) = v;
                }
            }
    }
}

// ---------------------------------------------------------------------------
// fp16 single-pass tensor-core flash attention (causal) — unchanged from R10.
// Q fp16 (pre-scaled); K,V fp16. 128 q/CTA, KTILE=64, 8 warps,
// cp.async 3-stage K/V pipeline. smem 73.7 KB -> 2 CTAs/SM.
// ---------------------------------------------------------------------------
#define AQT 128
#define AKT 64
#define ALD 72

struct AttnSmem {
    __half Q[AQT*ALD];
    __half KV[3][2][AKT*ALD];          // stage, {Kh,Vh}
};
#define ATTN_SMEM_BYTES ((int)sizeof(AttnSmem))   // 73728

__global__ __launch_bounds__(256, 2) void attn_mma_kernel()
{
    extern __shared__ char smraw[];
    AttnSmem& s = *(AttnSmem*)smraw;

    const int tid = threadIdx.x, lane = tid & 31, w = tid >> 5;
    const int bh = blockIdx.y;
    const int qi = gridDim.x - 1 - blockIdx.x;
    const int q0 = qi * AQT;
    const size_t base = (size_t)bh * TT * DD;
    const __half* kvsrc[2] = { g_Kh + base, g_Vh + base };
    const __half* Qsrc = g_Qh + base;

    const int nk = 2 * qi + 2;

    const int kr0 = tid >> 3, kr1 = 32 + (tid >> 3);
    const int kc = (tid & 7) * 8;

    auto issue_kv = [&](int kt) {
        const int st = kt % 3;
        const int k0 = kt * AKT;
        #pragma unroll
        for (int t = 0; t < 2; t++) {
            cp16(smem_u32(&s.KV[st][t][kr0 * ALD + kc]),
                 kvsrc[t] + (size_t)(k0 + kr0) * DD + kc);
            cp16(smem_u32(&s.KV[st][t][kr1 * ALD + kc]),
                 kvsrc[t] + (size_t)(k0 + kr1) * DD + kc);
        }
    };

    issue_kv(0); CP_COMMIT();
    issue_kv(1); CP_COMMIT();

    #pragma unroll
    for (int l = 0; l < 4; l++) {
        int idx = l * 256 + tid;
        int r = idx >> 3, d0 = (idx & 7) * 8;
        *(uint4*)&s.Q[r * ALD + d0] = *(const uint4*)(Qsrc + (size_t)(q0 + r) * DD + d0);
    }
    __syncthreads();

    const int a_m = ((lane >> 3) & 1) * 8 + (lane & 7);
    const int a_k = (lane >> 4) * 8;
    const int b_n = (lane >> 4) * 8 + (lane & 7);
    const int b_k = ((lane >> 3) & 1) * 8;
    const int t_r = ((lane >> 3) & 1) * 8 + (lane & 7);
    const int t_c = (lane >> 4) * 8;

    uint32_t qh[4][4];
    #pragma unroll
    for (int ks = 0; ks < 4; ks++) {
        uint32_t qa = smem_u32(&s.Q[(w * 16 + a_m) * ALD + ks * 16 + a_k]);
        ldsm_x4(qh[ks][0], qh[ks][1], qh[ks][2], qh[ks][3], qa);
    }

    float oacc[8][4];
    #pragma unroll
    for (int i = 0; i < 8; i++)
        #pragma unroll
        for (int j = 0; j < 4; j++) oacc[i][j] = 0.0f;
    float mrun[2] = { -1e30f, -1e30f }, lsum[2] = { 0.0f, 0.0f };

    const int qrow = q0 + w * 16 + (lane >> 2);

    for (int kt = 0; kt < nk; kt++) {
        const int k0 = kt * AKT;
        CP_WAIT(1);
        __syncthreads();
        if (kt + 2 < nk) issue_kv(kt + 2);
        CP_COMMIT();

        const int st = kt % 3;
        const __half* Khs = s.KV[st][0];
        const __half* Vhs = s.KV[st][1];

        // ---- S = Q K^T ----
        float sacc[8][4];
        #pragma unroll
        for (int i = 0; i < 8; i++)
            #pragma unroll
            for (int j = 0; j < 4; j++) sacc[i][j] = 0.0f;

        #pragma unroll
        for (int nbp = 0; nbp < 4; nbp++) {
            #pragma unroll
            for (int ks = 0; ks < 4; ks++) {
                uint32_t kh4[4];
                uint32_t ka = smem_u32(Khs + (nbp * 16 + b_n) * ALD + ks * 16 + b_k);
                ldsm_x4(kh4[0], kh4[1], kh4[2], kh4[3], ka);
                #pragma unroll
                for (int hf = 0; hf < 2; hf++) {
                    const int nb = nbp * 2 + hf;
                    uint32_t bh2[2] = { kh4[hf*2], kh4[hf*2+1] };
                    mma_f16(sacc[nb], qh[ks], bh2);
                }
            }
        }

        // ---- causal mask ----
        if (k0 + 63 > qrow) {
            #pragma unroll
            for (int nb = 0; nb < 8; nb++)
                #pragma unroll
                for (int c = 0; c < 4; c++) {
                    const int kg = k0 + nb * 8 + (lane & 3) * 2 + (c & 1);
                    const int qg = qrow + ((c >= 2) ? 8 : 0);
                    if (kg > qg) sacc[nb][c] = -1e30f;
                }
        }

        // ---- online softmax ----
        #pragma unroll
        for (int r = 0; r < 2; r++) {
            float tm = -1e30f;
            #pragma unroll
            for (int nb = 0; nb < 8; nb++)
                tm = fmaxf(tm, fmaxf(sacc[nb][2*r], sacc[nb][2*r+1]));
            tm = fmaxf(tm, __shfl_xor_sync(0xffffffffu, tm, 1));
            tm = fmaxf(tm, __shfl_xor_sync(0xffffffffu, tm, 2));
            const float mn = fmaxf(mrun[r], tm);
            const float al = __expf(mrun[r] - mn);
            mrun[r] = mn;
            float rs = 0.0f;
            #pragma unroll
            for (int nb = 0; nb < 8; nb++) {
                float p0 = __expf(sacc[nb][2*r]   - mn);
                float p1 = __expf(sacc[nb][2*r+1] - mn);
                sacc[nb][2*r] = p0; sacc[nb][2*r+1] = p1;
                rs += p0 + p1;
            }
            rs += __shfl_xor_sync(0xffffffffu, rs, 1);
            rs += __shfl_xor_sync(0xffffffffu, rs, 2);
            lsum[r] = lsum[r] * al + rs;
            #pragma unroll
            for (int dn = 0; dn < 8; dn++) {
                oacc[dn][2*r] *= al; oacc[dn][2*r+1] *= al;
            }
        }

        // ---- O += P V (trans-ldmatrix V) ----
        #pragma unroll
        for (int j = 0; j < 4; j++) {
            uint32_t ah[4];
            ah[0] = packf2(sacc[2*j][0],   sacc[2*j][1]);
            ah[1] = packf2(sacc[2*j][2],   sacc[2*j][3]);
            ah[2] = packf2(sacc[2*j+1][0], sacc[2*j+1][1]);
            ah[3] = packf2(sacc[2*j+1][2], sacc[2*j+1][3]);
            #pragma unroll
            for (int dnp = 0; dnp < 4; dnp++) {
                uint32_t vh4[4];
                uint32_t va = smem_u32(Vhs + (j * 16 + t_r) * ALD + dnp * 16 + t_c);
                ldsm_x4_t(vh4[0], vh4[1], vh4[2], vh4[3], va);
                #pragma unroll
                for (int hf = 0; hf < 2; hf++) {
                    const int dn = dnp * 2 + hf;
                    uint32_t bh2[2] = { vh4[hf*2], vh4[hf*2+1] };
                    mma_f16(oacc[dn], ah, bh2);
                }
            }
        }
    }

    // ---- epilogue: normalize, write fp16 O in [B*T, C] ----
    const int b = bh >> 4, h = bh & 15;
    #pragma unroll
    for (int r = 0; r < 2; r++) {
        const float inv = 1.0f / lsum[r];
        const int row = q0 + w * 16 + (lane >> 2) + r * 8;
        const size_t off = (size_t)(b * TT + row) * CC + h * DD;
        #pragma unroll
        for (int dn = 0; dn < 8; dn++) {
            const int col = dn * 8 + (lane & 3) * 2;
            *(uint32_t*)(g_Oh + off + col) =
                packf2(oacc[dn][2*r] * inv, oacc[dn][2*r+1] * inv);
        }
    }
}

// ---------------------------------------------------------------------------
extern "C" void kernel_launch(void* const* d_in, const int* in_sizes, int n_in,
                              void* d_out, int out_size)
{
    const float* x     = (const float*)d_in[0];
    const float* wqkv  = (const float*)d_in[1];
    const float* wproj = (const float*)d_in[2];
    float* out = (float*)d_out;

    cudaFuncSetAttribute((const void*)attn_mma_kernel,
                         cudaFuncAttributeMaxDynamicSharedMemorySize, ATTN_SMEM_BYTES);
    cudaFuncSetAttribute((const void*)mma_gemm_kernel<0>,
                         cudaFuncAttributeMaxDynamicSharedMemorySize, GEMM_SMEM_BYTES);
    cudaFuncSetAttribute((const void*)mma_gemm_kernel<1>,
                         cudaFuncAttributeMaxDynamicSharedMemorySize, GEMM_SMEM_BYTES);

    __half *xh, *wqh, *wph, *oh;
    cudaGetSymbolAddress((void**)&xh,  g_Xh);
    cudaGetSymbolAddress((void**)&wqh, g_Wqh);
    cudaGetSymbolAddress((void**)&wph, g_Wph);
    cudaGetSymbolAddress((void**)&oh,  g_Oh);

    convert_all_kernel<<<(N4_ALL + 255)/256, 256>>>(x, wqkv, wproj);

    mma_gemm_kernel<0><<<dim3(NQKV/256, MM/128), GEMM_THREADS, GEMM_SMEM_BYTES>>>(
        xh, wqh, nullptr);

    attn_mma_kernel<<<dim3(TT/AQT, BB*HH), 256, ATTN_SMEM_BYTES>>>();

    mma_gemm_kernel<1><<<dim3(CC/256, MM/128), GEMM_THREADS, GEMM_SMEM_BYTES>>>(
        oh, wph, out);
}

// round 12
// speedup vs baseline: 1.9945x; 1.0500x over previous
#include <cuda_runtime.h>
#include <cuda_fp16.h>
#include <cstdint>
#include <math.h>

// Problem constants
#define BB 4
#define TT 2048
#define CC 1024
#define HH 16
#define DD 64
#define MM (BB*TT)          // 8192
#define NQKV (3*CC)         // 3072

// ---------------------------------------------------------------------------
// Scratch (__device__ globals; no allocation allowed)
// ---------------------------------------------------------------------------
__device__ __half g_Qh[BB*HH*TT*DD];          // fp16, pre-scaled by 0.125
__device__ __half g_Kh[BB*HH*TT*DD];
__device__ __half g_Vh[BB*HH*TT*DD];
__device__ __half g_Xh[MM*CC];                // x as fp16
__device__ __half g_Wqh[NQKV*CC];             // w_qkv fp16
__device__ __half g_Wph[CC*CC];               // w_proj fp16
__device__ __half g_Oh[MM*CC];                // attn out fp16, [B*T, C]

// ---------------------------------------------------------------------------
// helpers
// ---------------------------------------------------------------------------
__device__ __forceinline__ uint32_t smem_u32(const void* p) {
    uint32_t a;
    asm("{ .reg .u64 t; cvta.to.shared.u64 t, %1; cvt.u32.u64 %0, t; }" : "=r"(a) : "l"(p));
    return a;
}
__device__ __forceinline__ void ldsm_x4(uint32_t& r0, uint32_t& r1, uint32_t& r2,
                                        uint32_t& r3, uint32_t addr) {
    asm volatile("ldmatrix.sync.aligned.m8n8.x4.shared.b16 {%0,%1,%2,%3}, [%4];"
                 : "=r"(r0), "=r"(r1), "=r"(r2), "=r"(r3) : "r"(addr));
}
__device__ __forceinline__ void ldsm_x4_t(uint32_t& r0, uint32_t& r1, uint32_t& r2,
                                          uint32_t& r3, uint32_t addr) {
    asm volatile("ldmatrix.sync.aligned.m8n8.x4.trans.shared.b16 {%0,%1,%2,%3}, [%4];"
                 : "=r"(r0), "=r"(r1), "=r"(r2), "=r"(r3) : "r"(addr));
}
__device__ __forceinline__ void mma_f16(float* c, const uint32_t* a, const uint32_t* b) {
    asm volatile("mma.sync.aligned.m16n8k16.row.col.f32.f16.f16.f32 "
                 "{%0,%1,%2,%3}, {%4,%5,%6,%7}, {%8,%9}, {%0,%1,%2,%3};"
                 : "+f"(c[0]), "+f"(c[1]), "+f"(c[2]), "+f"(c[3])
                 : "r"(a[0]), "r"(a[1]), "r"(a[2]), "r"(a[3]), "r"(b[0]), "r"(b[1]));
}
__device__ __forceinline__ void cp16(uint32_t dst, const void* src) {
    asm volatile("cp.async.cg.shared.global [%0], [%1], 16;" :: "r"(dst), "l"(src));
}
#define CP_COMMIT() asm volatile("cp.async.commit_group;" ::: "memory")
#define CP_WAIT(N)  asm volatile("cp.async.wait_group %0;" :: "n"(N) : "memory")

__device__ __forceinline__ uint32_t packf2(float x, float y) {
    __half2 t = __floats2half2_rn(x, y);   // x -> low half
    return *reinterpret_cast<uint32_t*>(&t);
}

// ---------------------------------------------------------------------------
// fused fp32 -> fp16 conversion (x, w_qkv, w_proj in one launch)
// ---------------------------------------------------------------------------
#define N4_X    (MM*CC/4)      // 2097152
#define N4_WQ   (NQKV*CC/4)    //  786432
#define N4_WP   (CC*CC/4)      //  262144
#define N4_ALL  (N4_X + N4_WQ + N4_WP)

__global__ __launch_bounds__(256) void convert_all_kernel(
    const float* __restrict__ x, const float* __restrict__ wq,
    const float* __restrict__ wp)
{
    int i = blockIdx.x * blockDim.x + threadIdx.x;
    if (i >= N4_ALL) return;
    const float* src; __half* dst; int j;
    if (i < N4_X)               { src = x;  dst = g_Xh;  j = i; }
    else if (i < N4_X + N4_WQ)  { src = wq; dst = g_Wqh; j = i - N4_X; }
    else                        { src = wp; dst = g_Wph; j = i - N4_X - N4_WQ; }
    float4 v = ((const float4*)src)[j];
    ((uint32_t*)dst)[j*2+0] = packf2(v.x, v.y);
    ((uint32_t*)dst)[j*2+1] = packf2(v.z, v.w);
}

// ---------------------------------------------------------------------------
// HMMA fp16 single-pass GEMM: C[m,n] = sum_k Ah[m,k]*Bh[n,k]
// 256 threads / 8 warps, warp tile 32x64 (4m x 2n), CTA 128x128, BK=64,
// 3-stage cp.async, smem 110.6 KB -> 2 CTAs/SM (cross-CTA latency hiding).
// MODE 0: Q -> fp16 scaled 0.125, K/V fp16, [B,H,T,D]. MODE 1: fp32 out [M,1024].
// ---------------------------------------------------------------------------
#define BKG 64
#define LDG_ 72
#define TILEA (128*LDG_)                  // 9216 halves
#define TILEB (128*LDG_)                  // 9216 halves
#define STAGEG (TILEA + TILEB)            // 18432 halves
#define NSTG 3
#define GEMM_SMEM_BYTES (NSTG*STAGEG*2)   // 110592 B
#define GEMM_THREADS 256

template<int MODE>
__global__ __launch_bounds__(GEMM_THREADS, 2) void mma_gemm_kernel(
    const __half* __restrict__ Ah, const __half* __restrict__ Bh,
    float* __restrict__ out)
{
    extern __shared__ __half sm[];
    const uint32_t smb = smem_u32(sm);
    const int tid = threadIdx.x;
    const int lane = tid & 31, wid = tid >> 5;     // wid 0..7
    const int wm = (wid >> 1) * 32;                // 0,32,64,96
    const int wn = (wid & 1) * 64;                 // 0,64
    const int n0 = blockIdx.x * 128;
    const int m0 = blockIdx.y * 128;

    const __half* Asrc = Ah + (size_t)m0 * CC;
    const __half* Bsrc = Bh + (size_t)n0 * CC;

    const int NCH = CC / BKG;   // 16

    float acc[2][8][4];
    #pragma unroll
    for (int a = 0; a < 2; a++)
        #pragma unroll
        for (int b = 0; b < 8; b++)
            #pragma unroll
            for (int c = 0; c < 4; c++) acc[a][b][c] = 0.0f;

    const int a_m = ((lane >> 3) & 1) * 8 + (lane & 7);
    const int a_k = (lane >> 4) * 8;
    const int b_n = (lane >> 4) * 8 + (lane & 7);
    const int b_k = ((lane >> 3) & 1) * 8;

    // one 64-K chunk: A 128x64 (1024 cp16) + B 128x64 (1024 cp16); 8 cp16/thread
    auto issue_chunk = [&](int ch) {
        const uint32_t sbase = smb + (uint32_t)(ch % NSTG) * (STAGEG * 2);
        const int k0 = ch * BKG;
        #pragma unroll
        for (int l = 0; l < 8; l++) {
            const int o = l * GEMM_THREADS + tid;     // 0..2047
            const int r = (o >> 3) & 127;
            const int c = (o & 7) * 8;
            if (o < 1024)
                cp16(sbase + (uint32_t)(r * LDG_ + c) * 2,
                     Asrc + (size_t)r * CC + k0 + c);
            else
                cp16(sbase + (uint32_t)(TILEA + r * LDG_ + c) * 2,
                     Bsrc + (size_t)r * CC + k0 + c);
        }
    };

    issue_chunk(0); CP_COMMIT();
    issue_chunk(1); CP_COMMIT();

    for (int ch = 0; ch < NCH; ch++) {
        CP_WAIT(1);
        __syncthreads();
        if (ch + 2 < NCH) issue_chunk(ch + 2);
        CP_COMMIT();

        const uint32_t buf = smb + (uint32_t)(ch % NSTG) * (STAGEG * 2);

        #pragma unroll
        for (int kk = 0; kk < BKG; kk += 16) {
            uint32_t aH[2][4], bH[4][4];
            #pragma unroll
            for (int mi = 0; mi < 2; mi++) {
                const int m = wm + mi * 16 + a_m;
                ldsm_x4(aH[mi][0], aH[mi][1], aH[mi][2], aH[mi][3],
                        buf + (uint32_t)(m * LDG_ + kk + a_k) * 2);
            }
            #pragma unroll
            for (int ni = 0; ni < 4; ni++) {
                const int n = wn + ni * 16 + b_n;
                ldsm_x4(bH[ni][0], bH[ni][1], bH[ni][2], bH[ni][3],
                        buf + (uint32_t)(TILEA + n * LDG_ + kk + b_k) * 2);
            }
            #pragma unroll
            for (int mi = 0; mi < 2; mi++)
                #pragma unroll
                for (int nj = 0; nj < 8; nj++) {
                    uint32_t bh[2] = { bH[nj >> 1][(nj & 1) * 2], bH[nj >> 1][(nj & 1) * 2 + 1] };
                    mma_f16(acc[mi][nj], aH[mi], bh);
                }
        }
    }

    // epilogue
    if (MODE == 0) {
        const int which = n0 >> 10;    // 128-col range never straddles a boundary
        __half* dst = (which == 0) ? g_Qh : ((which == 1) ? g_Kh : g_Vh);
        const float scl = (which == 0) ? 0.125f : 1.0f;
        #pragma unroll
        for (int mi = 0; mi < 2; mi++)
            #pragma unroll
            for (int nj = 0; nj < 8; nj++) {
                const int row0 = m0 + wm + mi * 16 + (lane >> 2);
                const int col  = n0 + wn + nj * 8 + (lane & 3) * 2;
                const int o = col & 1023, hd = o >> 6, d = o & 63;
                #pragma unroll
                for (int h = 0; h < 2; h++) {
                    const int row = row0 + h * 8;
                    const int b = row >> 11, t = row & 2047;
                    const size_t off = ((size_t)(b * HH + hd) * TT + t) * DD + d;
                    *(uint32_t*)(dst + off) =
                        packf2(acc[mi][nj][h*2] * scl, acc[mi][nj][h*2+1] * scl);
                }
            }
    } else {
        #pragma unroll
        for (int mi = 0; mi < 2; mi++)
            #pragma unroll
            for (int nj = 0; nj < 8; nj++) {
                const int row0 = m0 + wm + mi * 16 + (lane >> 2);
                const int col  = n0 + wn + nj * 8 + (lane & 3) * 2;
                #pragma unroll
                for (int h = 0; h < 2; h++) {
                    const int row = row0 + h * 8;
                    float2 v = make_float2(acc[mi][nj][h*2], acc[mi][nj][h*2+1]);
                    *(float2*)(out + (size_t)row * CC + col) = v;
                }
            }
    }
}

// ---------------------------------------------------------------------------
// fp16 single-pass tensor-core flash attention (causal) — unchanged.
// Q fp16 (pre-scaled); K,V fp16. 128 q/CTA, KTILE=64, 8 warps,
// cp.async 3-stage K/V pipeline. smem 73.7 KB -> 2 CTAs/SM.
// ---------------------------------------------------------------------------
#define AQT 128
#define AKT 64
#define ALD 72

struct AttnSmem {
    __half Q[AQT*ALD];
    __half KV[3][2][AKT*ALD];          // stage, {Kh,Vh}
};
#define ATTN_SMEM_BYTES ((int)sizeof(AttnSmem))   // 73728

__global__ __launch_bounds__(256, 2) void attn_mma_kernel()
{
    extern __shared__ char smraw[];
    AttnSmem& s = *(AttnSmem*)smraw;

    const int tid = threadIdx.x, lane = tid & 31, w = tid >> 5;
    const int bh = blockIdx.y;
    const int qi = gridDim.x - 1 - blockIdx.x;
    const int q0 = qi * AQT;
    const size_t base = (size_t)bh * TT * DD;
    const __half* kvsrc[2] = { g_Kh + base, g_Vh + base };
    const __half* Qsrc = g_Qh + base;

    const int nk = 2 * qi + 2;

    const int kr0 = tid >> 3, kr1 = 32 + (tid >> 3);
    const int kc = (tid & 7) * 8;

    auto issue_kv = [&](int kt) {
        const int st = kt % 3;
        const int k0 = kt * AKT;
        #pragma unroll
        for (int t = 0; t < 2; t++) {
            cp16(smem_u32(&s.KV[st][t][kr0 * ALD + kc]),
                 kvsrc[t] + (size_t)(k0 + kr0) * DD + kc);
            cp16(smem_u32(&s.KV[st][t][kr1 * ALD + kc]),
                 kvsrc[t] + (size_t)(k0 + kr1) * DD + kc);
        }
    };

    issue_kv(0); CP_COMMIT();
    issue_kv(1); CP_COMMIT();

    #pragma unroll
    for (int l = 0; l < 4; l++) {
        int idx = l * 256 + tid;
        int r = idx >> 3, d0 = (idx & 7) * 8;
        *(uint4*)&s.Q[r * ALD + d0] = *(const uint4*)(Qsrc + (size_t)(q0 + r) * DD + d0);
    }
    __syncthreads();

    const int a_m = ((lane >> 3) & 1) * 8 + (lane & 7);
    const int a_k = (lane >> 4) * 8;
    const int b_n = (lane >> 4) * 8 + (lane & 7);
    const int b_k = ((lane >> 3) & 1) * 8;
    const int t_r = ((lane >> 3) & 1) * 8 + (lane & 7);
    const int t_c = (lane >> 4) * 8;

    uint32_t qh[4][4];
    #pragma unroll
    for (int ks = 0; ks < 4; ks++) {
        uint32_t qa = smem_u32(&s.Q[(w * 16 + a_m) * ALD + ks * 16 + a_k]);
        ldsm_x4(qh[ks][0], qh[ks][1], qh[ks][2], qh[ks][3], qa);
    }

    float oacc[8][4];
    #pragma unroll
    for (int i = 0; i < 8; i++)
        #pragma unroll
        for (int j = 0; j < 4; j++) oacc[i][j] = 0.0f;
    float mrun[2] = { -1e30f, -1e30f }, lsum[2] = { 0.0f, 0.0f };

    const int qrow = q0 + w * 16 + (lane >> 2);

    for (int kt = 0; kt < nk; kt++) {
        const int k0 = kt * AKT;
        CP_WAIT(1);
        __syncthreads();
        if (kt + 2 < nk) issue_kv(kt + 2);
        CP_COMMIT();

        const int st = kt % 3;
        const __half* Khs = s.KV[st][0];
        const __half* Vhs = s.KV[st][1];

        // ---- S = Q K^T ----
        float sacc[8][4];
        #pragma unroll
        for (int i = 0; i < 8; i++)
            #pragma unroll
            for (int j = 0; j < 4; j++) sacc[i][j] = 0.0f;

        #pragma unroll
        for (int nbp = 0; nbp < 4; nbp++) {
            #pragma unroll
            for (int ks = 0; ks < 4; ks++) {
                uint32_t kh4[4];
                uint32_t ka = smem_u32(Khs + (nbp * 16 + b_n) * ALD + ks * 16 + b_k);
                ldsm_x4(kh4[0], kh4[1], kh4[2], kh4[3], ka);
                #pragma unroll
                for (int hf = 0; hf < 2; hf++) {
                    const int nb = nbp * 2 + hf;
                    uint32_t bh2[2] = { kh4[hf*2], kh4[hf*2+1] };
                    mma_f16(sacc[nb], qh[ks], bh2);
                }
            }
        }

        // ---- causal mask ----
        if (k0 + 63 > qrow) {
            #pragma unroll
            for (int nb = 0; nb < 8; nb++)
                #pragma unroll
                for (int c = 0; c < 4; c++) {
                    const int kg = k0 + nb * 8 + (lane & 3) * 2 + (c & 1);
                    const int qg = qrow + ((c >= 2) ? 8 : 0);
                    if (kg > qg) sacc[nb][c] = -1e30f;
                }
        }

        // ---- online softmax ----
        #pragma unroll
        for (int r = 0; r < 2; r++) {
            float tm = -1e30f;
            #pragma unroll
            for (int nb = 0; nb < 8; nb++)
                tm = fmaxf(tm, fmaxf(sacc[nb][2*r], sacc[nb][2*r+1]));
            tm = fmaxf(tm, __shfl_xor_sync(0xffffffffu, tm, 1));
            tm = fmaxf(tm, __shfl_xor_sync(0xffffffffu, tm, 2));
            const float mn = fmaxf(mrun[r], tm);
            const float al = __expf(mrun[r] - mn);
            mrun[r] = mn;
            float rs = 0.0f;
            #pragma unroll
            for (int nb = 0; nb < 8; nb++) {
                float p0 = __expf(sacc[nb][2*r]   - mn);
                float p1 = __expf(sacc[nb][2*r+1] - mn);
                sacc[nb][2*r] = p0; sacc[nb][2*r+1] = p1;
                rs += p0 + p1;
            }
            rs += __shfl_xor_sync(0xffffffffu, rs, 1);
            rs += __shfl_xor_sync(0xffffffffu, rs, 2);
            lsum[r] = lsum[r] * al + rs;
            #pragma unroll
            for (int dn = 0; dn < 8; dn++) {
                oacc[dn][2*r] *= al; oacc[dn][2*r+1] *= al;
            }
        }

        // ---- O += P V (trans-ldmatrix V) ----
        #pragma unroll
        for (int j = 0; j < 4; j++) {
            uint32_t ah[4];
            ah[0] = packf2(sacc[2*j][0],   sacc[2*j][1]);
            ah[1] = packf2(sacc[2*j][2],   sacc[2*j][3]);
            ah[2] = packf2(sacc[2*j+1][0], sacc[2*j+1][1]);
            ah[3] = packf2(sacc[2*j+1][2], sacc[2*j+1][3]);
            #pragma unroll
            for (int dnp = 0; dnp < 4; dnp++) {
                uint32_t vh4[4];
                uint32_t va = smem_u32(Vhs + (j * 16 + t_r) * ALD + dnp * 16 + t_c);
                ldsm_x4_t(vh4[0], vh4[1], vh4[2], vh4[3], va);
                #pragma unroll
                for (int hf = 0; hf < 2; hf++) {
                    const int dn = dnp * 2 + hf;
                    uint32_t bh2[2] = { vh4[hf*2], vh4[hf*2+1] };
                    mma_f16(oacc[dn], ah, bh2);
                }
            }
        }
    }

    // ---- epilogue: normalize, write fp16 O in [B*T, C] ----
    const int b = bh >> 4, h = bh & 15;
    #pragma unroll
    for (int r = 0; r < 2; r++) {
        const float inv = 1.0f / lsum[r];
        const int row = q0 + w * 16 + (lane >> 2) + r * 8;
        const size_t off = (size_t)(b * TT + row) * CC + h * DD;
        #pragma unroll
        for (int dn = 0; dn < 8; dn++) {
            const int col = dn * 8 + (lane & 3) * 2;
            *(uint32_t*)(g_Oh + off + col) =
                packf2(oacc[dn][2*r] * inv, oacc[dn][2*r+1] * inv);
        }
    }
}

// ---------------------------------------------------------------------------
extern "C" void kernel_launch(void* const* d_in, const int* in_sizes, int n_in,
                              void* d_out, int out_size)
{
    const float* x     = (const float*)d_in[0];
    const float* wqkv  = (const float*)d_in[1];
    const float* wproj = (const float*)d_in[2];
    float* out = (float*)d_out;

    cudaFuncSetAttribute((const void*)attn_mma_kernel,
                         cudaFuncAttributeMaxDynamicSharedMemorySize, ATTN_SMEM_BYTES);
    cudaFuncSetAttribute((const void*)mma_gemm_kernel<0>,
                         cudaFuncAttributeMaxDynamicSharedMemorySize, GEMM_SMEM_BYTES);
    cudaFuncSetAttribute((const void*)mma_gemm_kernel<1>,
                         cudaFuncAttributeMaxDynamicSharedMemorySize, GEMM_SMEM_BYTES);

    __half *xh, *wqh, *wph, *oh;
    cudaGetSymbolAddress((void**)&xh,  g_Xh);
    cudaGetSymbolAddress((void**)&wqh, g_Wqh);
    cudaGetSymbolAddress((void**)&wph, g_Wph);
    cudaGetSymbolAddress((void**)&oh,  g_Oh);

    convert_all_kernel<<<(N4_ALL + 255)/256, 256>>>(x, wqkv, wproj);

    mma_gemm_kernel<0><<<dim3(NQKV/128, MM/128), GEMM_THREADS, GEMM_SMEM_BYTES>>>(
        xh, wqh, nullptr);

    attn_mma_kernel<<<dim3(TT/AQT, BB*HH), 256, ATTN_SMEM_BYTES>>>();

    mma_gemm_kernel<1><<<dim3(CC/128, MM/128), GEMM_THREADS, GEMM_SMEM_BYTES>>>(
        oh, wph, out);
}

// round 13
// speedup vs baseline: 2.0414x; 1.0235x over previous
#include <cuda_runtime.h>
#include <cuda_fp16.h>
#include <cstdint>
#include <math.h>

// Problem constants
#define BB 4
#define TT 2048
#define CC 1024
#define HH 16
#define DD 64
#define MM (BB*TT)          // 8192
#define NQKV (3*CC)         // 3072

// ---------------------------------------------------------------------------
// Scratch (__device__ globals; no allocation allowed)
// ---------------------------------------------------------------------------
__device__ __half g_Qh[BB*HH*TT*DD];          // fp16, pre-scaled by 0.125*log2(e)
__device__ __half g_Kh[BB*HH*TT*DD];
__device__ __half g_Vh[BB*HH*TT*DD];
__device__ __half g_Xh[MM*CC];                // x as fp16
__device__ __half g_Wqh[NQKV*CC];             // w_qkv fp16
__device__ __half g_Wph[CC*CC];               // w_proj fp16
__device__ __half g_Oh[MM*CC];                // attn out fp16, [B*T, C]

// ---------------------------------------------------------------------------
// helpers
// ---------------------------------------------------------------------------
__device__ __forceinline__ uint32_t smem_u32(const void* p) {
    uint32_t a;
    asm("{ .reg .u64 t; cvta.to.shared.u64 t, %1; cvt.u32.u64 %0, t; }" : "=r"(a) : "l"(p));
    return a;
}
__device__ __forceinline__ void ldsm_x4(uint32_t& r0, uint32_t& r1, uint32_t& r2,
                                        uint32_t& r3, uint32_t addr) {
    asm volatile("ldmatrix.sync.aligned.m8n8.x4.shared.b16 {%0,%1,%2,%3}, [%4];"
                 : "=r"(r0), "=r"(r1), "=r"(r2), "=r"(r3) : "r"(addr));
}
__device__ __forceinline__ void ldsm_x4_t(uint32_t& r0, uint32_t& r1, uint32_t& r2,
                                          uint32_t& r3, uint32_t addr) {
    asm volatile("ldmatrix.sync.aligned.m8n8.x4.trans.shared.b16 {%0,%1,%2,%3}, [%4];"
                 : "=r"(r0), "=r"(r1), "=r"(r2), "=r"(r3) : "r"(addr));
}
__device__ __forceinline__ void mma_f16(float* c, const uint32_t* a, const uint32_t* b) {
    asm volatile("mma.sync.aligned.m16n8k16.row.col.f32.f16.f16.f32 "
                 "{%0,%1,%2,%3}, {%4,%5,%6,%7}, {%8,%9}, {%0,%1,%2,%3};"
                 : "+f"(c[0]), "+f"(c[1]), "+f"(c[2]), "+f"(c[3])
                 : "r"(a[0]), "r"(a[1]), "r"(a[2]), "r"(a[3]), "r"(b[0]), "r"(b[1]));
}
__device__ __forceinline__ void cp16(uint32_t dst, const void* src) {
    asm volatile("cp.async.cg.shared.global [%0], [%1], 16;" :: "r"(dst), "l"(src));
}
#define CP_COMMIT() asm volatile("cp.async.commit_group;" ::: "memory")
#define CP_WAIT(N)  asm volatile("cp.async.wait_group %0;" :: "n"(N) : "memory")

__device__ __forceinline__ uint32_t packf2(float x, float y) {
    __half2 t = __floats2half2_rn(x, y);   // x -> low half
    return *reinterpret_cast<uint32_t*>(&t);
}

// ---------------------------------------------------------------------------
// fused fp32 -> fp16 conversion (x, w_qkv, w_proj in one launch)
// ---------------------------------------------------------------------------
#define N4_X    (MM*CC/4)      // 2097152
#define N4_WQ   (NQKV*CC/4)    //  786432
#define N4_WP   (CC*CC/4)      //  262144
#define N4_ALL  (N4_X + N4_WQ + N4_WP)

__global__ __launch_bounds__(256) void convert_all_kernel(
    const float* __restrict__ x, const float* __restrict__ wq,
    const float* __restrict__ wp)
{
    int i = blockIdx.x * blockDim.x + threadIdx.x;
    if (i >= N4_ALL) return;
    const float* src; __half* dst; int j;
    if (i < N4_X)               { src = x;  dst = g_Xh;  j = i; }
    else if (i < N4_X + N4_WQ)  { src = wq; dst = g_Wqh; j = i - N4_X; }
    else                        { src = wp; dst = g_Wph; j = i - N4_X - N4_WQ; }
    float4 v = ((const float4*)src)[j];
    uint2 o;
    o.x = packf2(v.x, v.y);
    o.y = packf2(v.z, v.w);
    ((uint2*)dst)[j] = o;
}

// ---------------------------------------------------------------------------
// HMMA fp16 single-pass GEMM: C[m,n] = sum_k Ah[m,k]*Bh[n,k]
// 256 threads / 8 warps, warp tile 32x64 (4m x 2n), CTA 128x128, BK=64,
// 3-stage cp.async, smem 110.6 KB -> 2 CTAs/SM.
// MODE 0: Q -> fp16 scaled 0.125*log2e, K/V fp16, [B,H,T,D]. MODE 1: fp32 out.
// ---------------------------------------------------------------------------
#define BKG 64
#define LDG_ 72
#define TILEA (128*LDG_)                  // 9216 halves
#define TILEB (128*LDG_)                  // 9216 halves
#define STAGEG (TILEA + TILEB)            // 18432 halves
#define NSTG 3
#define GEMM_SMEM_BYTES (NSTG*STAGEG*2)   // 110592 B
#define GEMM_THREADS 256
#define LOG2E 1.44269504088896f

template<int MODE>
__global__ __launch_bounds__(GEMM_THREADS, 2) void mma_gemm_kernel(
    const __half* __restrict__ Ah, const __half* __restrict__ Bh,
    float* __restrict__ out)
{
    extern __shared__ __half sm[];
    const uint32_t smb = smem_u32(sm);
    const int tid = threadIdx.x;
    const int lane = tid & 31, wid = tid >> 5;     // wid 0..7
    const int wm = (wid >> 1) * 32;                // 0,32,64,96
    const int wn = (wid & 1) * 64;                 // 0,64
    const int n0 = blockIdx.x * 128;
    const int m0 = blockIdx.y * 128;

    const __half* Asrc = Ah + (size_t)m0 * CC;
    const __half* Bsrc = Bh + (size_t)n0 * CC;

    const int NCH = CC / BKG;   // 16

    float acc[2][8][4];
    #pragma unroll
    for (int a = 0; a < 2; a++)
        #pragma unroll
        for (int b = 0; b < 8; b++)
            #pragma unroll
            for (int c = 0; c < 4; c++) acc[a][b][c] = 0.0f;

    const int a_m = ((lane >> 3) & 1) * 8 + (lane & 7);
    const int a_k = (lane >> 4) * 8;
    const int b_n = (lane >> 4) * 8 + (lane & 7);
    const int b_k = ((lane >> 3) & 1) * 8;

    // one 64-K chunk: A 128x64 (1024 cp16) + B 128x64 (1024 cp16); 8 cp16/thread
    auto issue_chunk = [&](int st, int ch) {
        const uint32_t sbase = smb + (uint32_t)st * (STAGEG * 2);
        const int k0 = ch * BKG;
        #pragma unroll
        for (int l = 0; l < 8; l++) {
            const int o = l * GEMM_THREADS + tid;     // 0..2047
            const int r = (o >> 3) & 127;
            const int c = (o & 7) * 8;
            if (o < 1024)
                cp16(sbase + (uint32_t)(r * LDG_ + c) * 2,
                     Asrc + (size_t)r * CC + k0 + c);
            else
                cp16(sbase + (uint32_t)(TILEA + r * LDG_ + c) * 2,
                     Bsrc + (size_t)r * CC + k0 + c);
        }
    };

    issue_chunk(0, 0); CP_COMMIT();
    issue_chunk(1, 1); CP_COMMIT();

    int st_cur = 0, st_pf = 2;
    for (int ch = 0; ch < NCH; ch++) {
        CP_WAIT(1);
        __syncthreads();
        if (ch + 2 < NCH) issue_chunk(st_pf, ch + 2);
        CP_COMMIT();

        const uint32_t buf = smb + (uint32_t)st_cur * (STAGEG * 2);
        if (++st_cur == NSTG) st_cur = 0;
        if (++st_pf == NSTG) st_pf = 0;

        #pragma unroll
        for (int kk = 0; kk < BKG; kk += 16) {
            uint32_t aH[2][4], bH[4][4];
            #pragma unroll
            for (int mi = 0; mi < 2; mi++) {
                const int m = wm + mi * 16 + a_m;
                ldsm_x4(aH[mi][0], aH[mi][1], aH[mi][2], aH[mi][3],
                        buf + (uint32_t)(m * LDG_ + kk + a_k) * 2);
            }
            #pragma unroll
            for (int ni = 0; ni < 4; ni++) {
                const int n = wn + ni * 16 + b_n;
                ldsm_x4(bH[ni][0], bH[ni][1], bH[ni][2], bH[ni][3],
                        buf + (uint32_t)(TILEA + n * LDG_ + kk + b_k) * 2);
            }
            #pragma unroll
            for (int mi = 0; mi < 2; mi++)
                #pragma unroll
                for (int nj = 0; nj < 8; nj++) {
                    uint32_t bh[2] = { bH[nj >> 1][(nj & 1) * 2], bH[nj >> 1][(nj & 1) * 2 + 1] };
                    mma_f16(acc[mi][nj], aH[mi], bh);
                }
        }
    }

    // epilogue
    if (MODE == 0) {
        const int which = n0 >> 10;    // 128-col range never straddles a boundary
        __half* dst = (which == 0) ? g_Qh : ((which == 1) ? g_Kh : g_Vh);
        const float scl = (which == 0) ? (0.125f * LOG2E) : 1.0f;
        #pragma unroll
        for (int mi = 0; mi < 2; mi++)
            #pragma unroll
            for (int nj = 0; nj < 8; nj++) {
                const int row0 = m0 + wm + mi * 16 + (lane >> 2);
                const int col  = n0 + wn + nj * 8 + (lane & 3) * 2;
                const int o = col & 1023, hd = o >> 6, d = o & 63;
                #pragma unroll
                for (int h = 0; h < 2; h++) {
                    const int row = row0 + h * 8;
                    const int b = row >> 11, t = row & 2047;
                    const size_t off = ((size_t)(b * HH + hd) * TT + t) * DD + d;
                    *(uint32_t*)(dst + off) =
                        packf2(acc[mi][nj][h*2] * scl, acc[mi][nj][h*2+1] * scl);
                }
            }
    } else {
        #pragma unroll
        for (int mi = 0; mi < 2; mi++)
            #pragma unroll
            for (int nj = 0; nj < 8; nj++) {
                const int row0 = m0 + wm + mi * 16 + (lane >> 2);
                const int col  = n0 + wn + nj * 8 + (lane & 3) * 2;
                #pragma unroll
                for (int h = 0; h < 2; h++) {
                    const int row = row0 + h * 8;
                    float2 v = make_float2(acc[mi][nj][h*2], acc[mi][nj][h*2+1]);
                    *(float2*)(out + (size_t)row * CC + col) = v;
                }
            }
    }
}

// ---------------------------------------------------------------------------
// fp16 single-pass tensor-core flash attention (causal), exp2 softmax
// (log2e pre-folded into Q). 128 q/CTA, KTILE=64, 8 warps,
// cp.async 3-stage K/V pipeline. smem 73.7 KB -> 2 CTAs/SM.
// ---------------------------------------------------------------------------
#define AQT 128
#define AKT 64
#define ALD 72

struct AttnSmem {
    __half Q[AQT*ALD];
    __half KV[3][2][AKT*ALD];          // stage, {Kh,Vh}
};
#define ATTN_SMEM_BYTES ((int)sizeof(AttnSmem))   // 73728

__global__ __launch_bounds__(256, 2) void attn_mma_kernel()
{
    extern __shared__ char smraw[];
    AttnSmem& s = *(AttnSmem*)smraw;

    const int tid = threadIdx.x, lane = tid & 31, w = tid >> 5;
    const int bh = blockIdx.y;
    const int qi = gridDim.x - 1 - blockIdx.x;
    const int q0 = qi * AQT;
    const size_t base = (size_t)bh * TT * DD;
    const __half* kvsrc[2] = { g_Kh + base, g_Vh + base };
    const __half* Qsrc = g_Qh + base;

    const int nk = 2 * qi + 2;

    const int kr0 = tid >> 3, kr1 = 32 + (tid >> 3);
    const int kc = (tid & 7) * 8;

    auto issue_kv = [&](int st, int kt) {
        const int k0 = kt * AKT;
        #pragma unroll
        for (int t = 0; t < 2; t++) {
            cp16(smem_u32(&s.KV[st][t][kr0 * ALD + kc]),
                 kvsrc[t] + (size_t)(k0 + kr0) * DD + kc);
            cp16(smem_u32(&s.KV[st][t][kr1 * ALD + kc]),
                 kvsrc[t] + (size_t)(k0 + kr1) * DD + kc);
        }
    };

    issue_kv(0, 0); CP_COMMIT();
    issue_kv(1, 1); CP_COMMIT();

    #pragma unroll
    for (int l = 0; l < 4; l++) {
        int idx = l * 256 + tid;
        int r = idx >> 3, d0 = (idx & 7) * 8;
        *(uint4*)&s.Q[r * ALD + d0] = *(const uint4*)(Qsrc + (size_t)(q0 + r) * DD + d0);
    }
    __syncthreads();

    const int a_m = ((lane >> 3) & 1) * 8 + (lane & 7);
    const int a_k = (lane >> 4) * 8;
    const int b_n = (lane >> 4) * 8 + (lane & 7);
    const int b_k = ((lane >> 3) & 1) * 8;
    const int t_r = ((lane >> 3) & 1) * 8 + (lane & 7);
    const int t_c = (lane >> 4) * 8;

    uint32_t qh[4][4];
    #pragma unroll
    for (int ks = 0; ks < 4; ks++) {
        uint32_t qa = smem_u32(&s.Q[(w * 16 + a_m) * ALD + ks * 16 + a_k]);
        ldsm_x4(qh[ks][0], qh[ks][1], qh[ks][2], qh[ks][3], qa);
    }

    float oacc[8][4];
    #pragma unroll
    for (int i = 0; i < 8; i++)
        #pragma unroll
        for (int j = 0; j < 4; j++) oacc[i][j] = 0.0f;
    float mrun[2] = { -1e30f, -1e30f }, lsum[2] = { 0.0f, 0.0f };

    const int qrow = q0 + w * 16 + (lane >> 2);

    int st_cur = 0, st_pf = 2;
    for (int kt = 0; kt < nk; kt++) {
        const int k0 = kt * AKT;
        CP_WAIT(1);
        __syncthreads();
        if (kt + 2 < nk) issue_kv(st_pf, kt + 2);
        CP_COMMIT();

        const __half* Khs = s.KV[st_cur][0];
        const __half* Vhs = s.KV[st_cur][1];
        if (++st_cur == 3) st_cur = 0;
        if (++st_pf == 3) st_pf = 0;

        // ---- S = Q K^T  (Q carries 0.125*log2e) ----
        float sacc[8][4];
        #pragma unroll
        for (int i = 0; i < 8; i++)
            #pragma unroll
            for (int j = 0; j < 4; j++) sacc[i][j] = 0.0f;

        #pragma unroll
        for (int nbp = 0; nbp < 4; nbp++) {
            #pragma unroll
            for (int ks = 0; ks < 4; ks++) {
                uint32_t kh4[4];
                uint32_t ka = smem_u32(Khs + (nbp * 16 + b_n) * ALD + ks * 16 + b_k);
                ldsm_x4(kh4[0], kh4[1], kh4[2], kh4[3], ka);
                #pragma unroll
                for (int hf = 0; hf < 2; hf++) {
                    const int nb = nbp * 2 + hf;
                    uint32_t bh2[2] = { kh4[hf*2], kh4[hf*2+1] };
                    mma_f16(sacc[nb], qh[ks], bh2);
                }
            }
        }

        // ---- causal mask ----
        if (k0 + 63 > qrow) {
            #pragma unroll
            for (int nb = 0; nb < 8; nb++)
                #pragma unroll
                for (int c = 0; c < 4; c++) {
                    const int kg = k0 + nb * 8 + (lane & 3) * 2 + (c & 1);
                    const int qg = qrow + ((c >= 2) ? 8 : 0);
                    if (kg > qg) sacc[nb][c] = -1e30f;
                }
        }

        // ---- online softmax (base-2) ----
        #pragma unroll
        for (int r = 0; r < 2; r++) {
            float tm = -1e30f;
            #pragma unroll
            for (int nb = 0; nb < 8; nb++)
                tm = fmaxf(tm, fmaxf(sacc[nb][2*r], sacc[nb][2*r+1]));
            tm = fmaxf(tm, __shfl_xor_sync(0xffffffffu, tm, 1));
            tm = fmaxf(tm, __shfl_xor_sync(0xffffffffu, tm, 2));
            const float mn = fmaxf(mrun[r], tm);
            const float al = exp2f(mrun[r] - mn);
            mrun[r] = mn;
            float rs = 0.0f;
            #pragma unroll
            for (int nb = 0; nb < 8; nb++) {
                float p0 = exp2f(sacc[nb][2*r]   - mn);
                float p1 = exp2f(sacc[nb][2*r+1] - mn);
                sacc[nb][2*r] = p0; sacc[nb][2*r+1] = p1;
                rs += p0 + p1;
            }
            rs += __shfl_xor_sync(0xffffffffu, rs, 1);
            rs += __shfl_xor_sync(0xffffffffu, rs, 2);
            lsum[r] = lsum[r] * al + rs;
            #pragma unroll
            for (int dn = 0; dn < 8; dn++) {
                oacc[dn][2*r] *= al; oacc[dn][2*r+1] *= al;
            }
        }

        // ---- O += P V (trans-ldmatrix V) ----
        #pragma unroll
        for (int j = 0; j < 4; j++) {
            uint32_t ah[4];
            ah[0] = packf2(sacc[2*j][0],   sacc[2*j][1]);
            ah[1] = packf2(sacc[2*j][2],   sacc[2*j][3]);
            ah[2] = packf2(sacc[2*j+1][0], sacc[2*j+1][1]);
            ah[3] = packf2(sacc[2*j+1][2], sacc[2*j+1][3]);
            #pragma unroll
            for (int dnp = 0; dnp < 4; dnp++) {
                uint32_t vh4[4];
                uint32_t va = smem_u32(Vhs + (j * 16 + t_r) * ALD + dnp * 16 + t_c);
                ldsm_x4_t(vh4[0], vh4[1], vh4[2], vh4[3], va);
                #pragma unroll
                for (int hf = 0; hf < 2; hf++) {
                    const int dn = dnp * 2 + hf;
                    uint32_t bh2[2] = { vh4[hf*2], vh4[hf*2+1] };
                    mma_f16(oacc[dn], ah, bh2);
                }
            }
        }
    }

    // ---- epilogue: normalize, write fp16 O in [B*T, C] ----
    const int b = bh >> 4, h = bh & 15;
    #pragma unroll
    for (int r = 0; r < 2; r++) {
        const float inv = 1.0f / lsum[r];
        const int row = q0 + w * 16 + (lane >> 2) + r * 8;
        const size_t off = (size_t)(b * TT + row) * CC + h * DD;
        #pragma unroll
        for (int dn = 0; dn < 8; dn++) {
            const int col = dn * 8 + (lane & 3) * 2;
            *(uint32_t*)(g_Oh + off + col) =
                packf2(oacc[dn][2*r] * inv, oacc[dn][2*r+1] * inv);
        }
    }
}

// ---------------------------------------------------------------------------
extern "C" void kernel_launch(void* const* d_in, const int* in_sizes, int n_in,
                              void* d_out, int out_size)
{
    const float* x     = (const float*)d_in[0];
    const float* wqkv  = (const float*)d_in[1];
    const float* wproj = (const float*)d_in[2];
    float* out = (float*)d_out;

    cudaFuncSetAttribute((const void*)attn_mma_kernel,
                         cudaFuncAttributeMaxDynamicSharedMemorySize, ATTN_SMEM_BYTES);
    cudaFuncSetAttribute((const void*)mma_gemm_kernel<0>,
                         cudaFuncAttributeMaxDynamicSharedMemorySize, GEMM_SMEM_BYTES);
    cudaFuncSetAttribute((const void*)mma_gemm_kernel<1>,
                         cudaFuncAttributeMaxDynamicSharedMemorySize, GEMM_SMEM_BYTES);

    __half *xh, *wqh, *wph, *oh;
    cudaGetSymbolAddress((void**)&xh,  g_Xh);
    cudaGetSymbolAddress((void**)&wqh, g_Wqh);
    cudaGetSymbolAddress((void**)&wph, g_Wph);
    cudaGetSymbolAddress((void**)&oh,  g_Oh);

    convert_all_kernel<<<(N4_ALL + 255)/256, 256>>>(x, wqkv, wproj);

    mma_gemm_kernel<0><<<dim3(NQKV/128, MM/128), GEMM_THREADS, GEMM_SMEM_BYTES>>>(
        xh, wqh, nullptr);

    attn_mma_kernel<<<dim3(TT/AQT, BB*HH), 256, ATTN_SMEM_BYTES>>>();

    mma_gemm_kernel<1><<<dim3(CC/128, MM/128), GEMM_THREADS, GEMM_SMEM_BYTES>>>(
        oh, wph, out);
}